// round 4
// baseline (speedup 1.0000x reference)
#include <cuda_runtime.h>
#include <math.h>

// ---------------- problem constants ----------------
#define DIMK   1024
#define IMG_H  512
#define IMG_W  1408
#define CROPS  224
#define BB     2
#define NCC    6
#define NBB    32
#define NBOX   (BB*NBB)        // 64
#define NIMG   (NBOX*NCC)      // 384

// conv geometry
#define O1 56
#define O2 14
#define O3 7
#define N1 ((long long)NIMG*O1*O1)   // 1204224
#define N2 ((long long)NIMG*O2*O2)   // 75264
#define N3 ((long long)NIMG*O3*O3)   // 18816
#define K1 (3*7*7)     // 147
#define K2 (64*3*3)    // 576
#define K3 (256*3*3)   // 2304

// ---------------- scratch (device globals; no alloc) ----------------
__device__ float g_theta[NIMG*6];
__device__ int   g_valid[NIMG];
__device__ float g_crops[3LL*NIMG*CROPS*CROPS];     // [ch][img][y][x]
__device__ float g_h1[64LL*N1];                     // [oc][img*pos]
__device__ float g_h2[256LL*N2];
__device__ float g_h3[1024LL*N3];
__device__ float g_tok[(long long)NIMG*50*DIMK];
__device__ float g_M[DIMK*DIMK];
__device__ float g_Wvo[DIMK*DIMK];
__device__ float g_S[NIMG*DIMK];
__device__ float g_CTX[NIMG*DIMK];
__device__ float g_EMB[NIMG*DIMK];

// ---------------- theta / projection ----------------
__global__ void theta_kernel(const float* __restrict__ boxes,
                             const float* __restrict__ la,
                             const float* __restrict__ l2i,
                             const float* __restrict__ aug,
                             const float* __restrict__ thw,
                             const float* __restrict__ thb)
{
    int t = blockIdx.x*blockDim.x + threadIdx.x;
    if (t >= NIMG) return;
    int c = t % NCC; int n = t / NCC; int b = n / NBB; int nb = n % NBB;
    const float* bx = boxes + (b*NBB + nb)*9;

    float r[4];
    #pragma unroll
    for (int i = 0; i < 4; i++) {
        float s = thb[i];
        #pragma unroll
        for (int j = 0; j < 9; j++) s += bx[j]*thw[i*9+j];
        r[i] = tanhf(s);
    }

    const float* L = la + b*16;
    float cx = bx[0]-L[3], cy = bx[1]-L[7], cz = bx[2]-L[11];
    float a00=L[0],a01=L[1],a02=L[2],a10=L[4],a11=L[5],a12=L[6],a20=L[8],a21=L[9],a22=L[10];
    float det = a00*(a11*a22-a12*a21) - a01*(a10*a22-a12*a20) + a02*(a10*a21-a11*a20);
    float id = 1.f/det;
    float x = ((a11*a22-a12*a21)*cx + (a02*a21-a01*a22)*cy + (a01*a12-a02*a11)*cz)*id;
    float y = ((a12*a20-a10*a22)*cx + (a00*a22-a02*a20)*cy + (a02*a10-a00*a12)*cz)*id;
    float z = ((a10*a21-a11*a20)*cx + (a01*a20-a00*a21)*cy + (a00*a11-a01*a10)*cz)*id;

    const float* P = l2i + (b*NCC + c)*16;
    float px = P[0]*x + P[1]*y + P[2]*z  + P[3];
    float py = P[4]*x + P[5]*y + P[6]*z  + P[7];
    float pz = P[8]*x + P[9]*y + P[10]*z + P[11];
    float zz = fminf(fmaxf(pz, 1e-5f), 100000.f);
    float qx = px/zz, qy = py/zz;
    const float* A = aug + (b*NCC + c)*16;
    float ux = A[0]*qx + A[1]*qy + A[2]*zz + A[3];
    float uy = A[4]*qx + A[5]*qy + A[6]*zz + A[7];

    int on = (uy < (float)IMG_H) && (uy >= 0.f) && (ux < (float)IMG_W) && (ux >= 0.f);
    float ty = uy/(float)IMG_H*2.f - 1.f;
    float tx = ux/(float)IMG_W*2.f - 1.f;

    g_theta[t*6+0]=r[0]; g_theta[t*6+1]=r[1]; g_theta[t*6+2]=tx;
    g_theta[t*6+3]=r[2]; g_theta[t*6+4]=r[3]; g_theta[t*6+5]=ty;
    g_valid[t] = on;
}

// ---------------- grid sample -> crops ----------------
__global__ void sample_kernel(const float* __restrict__ imgs)
{
    long long idx = (long long)blockIdx.x*blockDim.x + threadIdx.x;
    long long total = (long long)NIMG*CROPS*CROPS;
    if (idx >= total) return;
    int x = (int)(idx % CROPS);
    int y = (int)((idx / CROPS) % CROPS);
    int ii = (int)(idx / (CROPS*CROPS));
    int c = ii % NCC; int n = ii / NCC; int b = n / NBB;

    float t0 = g_theta[ii*6+0], t1 = g_theta[ii*6+1], t2 = g_theta[ii*6+2];
    float t3 = g_theta[ii*6+3], t4 = g_theta[ii*6+4], t5 = g_theta[ii*6+5];

    float gx = (2.f*x + 1.f)/(float)CROPS - 1.f;
    float gy = (2.f*y + 1.f)/(float)CROPS - 1.f;
    float g0 = gx*t0 + gy*t1 + t2;
    float g1 = gx*t3 + gy*t4 + t5;
    float ixf = ((g0 + 1.f)*(float)IMG_W - 1.f)*0.5f;
    float iyf = ((g1 + 1.f)*(float)IMG_H - 1.f)*0.5f;
    float x0 = floorf(ixf), y0 = floorf(iyf);
    float wx = ixf - x0,    wy = iyf - y0;
    float x1 = x0 + 1.f,    y1 = y0 + 1.f;
    bool vx0 = (x0 >= 0.f) && (x0 <= (float)(IMG_W-1));
    bool vx1 = (x1 >= 0.f) && (x1 <= (float)(IMG_W-1));
    bool vy0 = (y0 >= 0.f) && (y0 <= (float)(IMG_H-1));
    bool vy1 = (y1 >= 0.f) && (y1 <= (float)(IMG_H-1));
    int xi0 = (int)fminf(fmaxf(x0,0.f),(float)(IMG_W-1));
    int xi1 = (int)fminf(fmaxf(x1,0.f),(float)(IMG_W-1));
    int yi0 = (int)fminf(fmaxf(y0,0.f),(float)(IMG_H-1));
    int yi1 = (int)fminf(fmaxf(y1,0.f),(float)(IMG_H-1));
    float w00=(1.f-wx)*(1.f-wy), w01=wx*(1.f-wy), w10=(1.f-wx)*wy, w11=wx*wy;

    const float* base = imgs + (long long)(b*NCC + c)*3LL*IMG_H*IMG_W;
    #pragma unroll
    for (int ch = 0; ch < 3; ch++) {
        const float* im = base + (long long)ch*IMG_H*IMG_W;
        float v00 = (vx0&&vy0) ? im[yi0*IMG_W + xi0] : 0.f;
        float v01 = (vx1&&vy0) ? im[yi0*IMG_W + xi1] : 0.f;
        float v10 = (vx0&&vy1) ? im[yi1*IMG_W + xi0] : 0.f;
        float v11 = (vx1&&vy1) ? im[yi1*IMG_W + xi1] : 0.f;
        g_crops[((long long)(ch*NIMG + ii)*CROPS + y)*CROPS + x] =
            v00*w00 + v01*w01 + v10*w10 + v11*w11;
    }
}

// ---------------- helpers ----------------
__device__ __forceinline__ unsigned f2tf32(float f) {
    unsigned u;
    asm("cvt.rna.tf32.f32 %0, %1;" : "=r"(u) : "f"(f));
    return u;
}
__device__ __forceinline__ void cpasync4(unsigned dst, const float* src, bool pred) {
    asm volatile("cp.async.ca.shared.global [%0], [%1], 4, %2;\n"
        :: "r"(dst), "l"(src), "r"(pred ? 4 : 0) : "memory");
}
__device__ __forceinline__ void cpasync16(unsigned dst, const float* src) {
    asm volatile("cp.async.cg.shared.global [%0], [%1], 16;\n"
        :: "r"(dst), "l"(src) : "memory");
}
#define CP_COMMIT() asm volatile("cp.async.commit_group;\n" ::: "memory")
#define CP_WAIT1()  asm volatile("cp.async.wait_group 1;\n" ::: "memory")

// =====================================================================
// Pipelined implicit-GEMM, tf32 tensor cores.
// C[M][N] = A[M][K] * B(K,N);  B materialized on the fly per LOADER.
// Block tile BM x 128 x 16, 3-stage cp.async pipeline, 256 threads.
// smem layouts are fragment-native: addr(m,k)=(m>>3)*128+k*8+(m&7)
// (lane addr = tg*8+g -> 32 distinct banks, conflict-free).
// LOADER: 0=dense B[k][n], 1=conv1 gather, 2=conv2 gather, 3=conv3 gather
// =====================================================================
template<int LOADER, int BM, bool RELU>
__global__ __launch_bounds__(256) void pgemm(
    const float* __restrict__ A, const float* __restrict__ B, float* __restrict__ C,
    int M, int N, int K, int lda, int ldb, int ldc)
{
    constexpr int ASTG = BM*16;
    __shared__ float As[3][ASTG];
    __shared__ float Bs[3][2048];

    const int tid = threadIdx.x;
    const int bx = blockIdx.x, by = blockIdx.y;

    // ---- per-thread B-gather context (n fixed per thread) ----
    const int nloc = tid & 127;
    const int ngl  = bx*128 + nloc;
    const int bdst0 = (nloc>>3)*128 + (nloc&7);   // + krow*8
    const int krow0 = tid >> 7;                   // 0 or 1; krow = krow0 + 2*i

    // conv contexts
    long long cv_base = 0;  int cv_yb = 0, cv_xb = 0;
    if (LOADER == 1) {
        int img = ngl/3136; int pos = ngl - img*3136;
        int oy = pos/56, ox = pos - oy*56;
        cv_yb = oy*4 - 1; cv_xb = ox*4 - 1;
        cv_base = (long long)img*(CROPS*CROPS);
    } else if (LOADER == 2) {
        int img = ngl/196; int pos = ngl - img*196;
        int oy = pos/14, ox = pos - oy*14;
        cv_base = (long long)img*3136 + (long long)(oy*4)*56 + ox*4;
    } else if (LOADER == 3) {
        int img = ngl/49; int pos = ngl - img*49;
        int oy = pos/7, ox = pos - oy*7;
        cv_yb = oy*2; cv_xb = ox*2;
        cv_base = (long long)img*196;
    }

    unsigned sA0 = (unsigned)__cvta_generic_to_shared(&As[0][0]);
    unsigned sB0 = (unsigned)__cvta_generic_to_shared(&Bs[0][0]);

    // ---- stage loader ----
    auto load_stage = [&](int st, int k0) {
        unsigned sa = sA0 + (unsigned)(st*ASTG*4);
        unsigned sb = sB0 + (unsigned)(st*2048*4);
        // A: BM*16 elements, 4B cp.async, coalesced along k
        #pragma unroll
        for (int i = 0; i < ASTG/256; i++) {
            int e = tid + i*256;
            int k = e & 15, m = e >> 4;
            int gc = k0 + k;
            const float* src = A + (long long)(by*BM + m)*lda + gc;
            unsigned dst = sa + (unsigned)(((m>>3)*128 + k*8 + (m&7))*4);
            cpasync4(dst, src, gc < K);
        }
        if (LOADER == 0) {
            // dense B: 16B chunks along n
            #pragma unroll
            for (int i = 0; i < 2; i++) {
                int cch = tid + i*256;
                int k = cch >> 5; int n4 = (cch & 31)*4;
                const float* src = B + (long long)(k0 + k)*ldb + bx*128 + n4;
                unsigned dst = sb + (unsigned)((((n4>>3)*128) + k*8 + (n4&7))*4);
                cpasync16(dst, src);
            }
        } else {
            #pragma unroll
            for (int i = 0; i < 8; i++) {
                int krow = krow0 + 2*i;
                int k = k0 + krow;
                unsigned dst = sb + (unsigned)((bdst0 + krow*8)*4);
                if (LOADER == 1) {
                    int ch = k/49; int rr = k - ch*49;
                    int ky = rr/7, kx = rr - ky*7;
                    int iy = cv_yb + ky, ix = cv_xb + kx;
                    bool p = (k < K) && (iy >= 0) && (iy < CROPS) && (ix >= 0) && (ix < CROPS);
                    const float* src = B + ((long long)ch*NIMG*(CROPS*CROPS) + cv_base + (long long)iy*CROPS + ix);
                    cpasync4(dst, src, p);
                } else if (LOADER == 2) {
                    int ic = k/9; int rr = k - ic*9;
                    int ky = rr/3, kx = rr - ky*3;
                    const float* src = B + ((long long)ic*N1 + cv_base + ky*56 + kx);
                    cpasync4(dst, src, true);
                } else {
                    int ic = k/9; int rr = k - ic*9;
                    int ky = rr/3, kx = rr - ky*3;
                    int iy = cv_yb + ky, ix = cv_xb + kx;
                    bool p = (iy < 14) && (ix < 14);
                    const float* src = B + ((long long)ic*N2 + cv_base + iy*14 + ix);
                    cpasync4(dst, src, p);
                }
            }
        }
    };

    // ---- warp/fragment config ----
    constexpr int WMC = BM/32;          // warps along M
    constexpr int WN  = 128/(8/WMC);    // warp tile N
    constexpr int NT  = WN/8;
    const int lane = tid & 31, warp = tid >> 5;
    const int wm = (warp % WMC)*32;
    const int wn = (warp / WMC)*WN;
    const int g  = lane >> 2, tg = lane & 3;

    float acc[2][NT][4];
    #pragma unroll
    for (int i=0;i<2;i++)
        #pragma unroll
        for (int j=0;j<NT;j++)
            #pragma unroll
            for (int q=0;q<4;q++) acc[i][j][q] = 0.f;

    const int T = (K + 15)/16;

    load_stage(0, 0);  CP_COMMIT();
    load_stage(1, 16); CP_COMMIT();

    for (int kt = 0; kt < T; kt++) {
        CP_WAIT1();
        __syncthreads();
        int kn = kt + 2;
        if (kn < T) load_stage(kn % 3, kn*16);
        CP_COMMIT();

        const float* as = As[kt % 3];
        const float* bs = Bs[kt % 3];
        #pragma unroll
        for (int ks = 0; ks < 16; ks += 8) {
            unsigned af[2][4];
            #pragma unroll
            for (int mt = 0; mt < 2; mt++) {
                int base = ((wm + mt*16)>>3)*128 + (ks+tg)*8 + g;
                af[mt][0] = f2tf32(as[base]);
                af[mt][1] = f2tf32(as[base+128]);
                af[mt][2] = f2tf32(as[base+32]);
                af[mt][3] = f2tf32(as[base+160]);
            }
            unsigned bf[NT][2];
            #pragma unroll
            for (int nt = 0; nt < NT; nt++) {
                int base = ((wn>>3) + nt)*128 + (ks+tg)*8 + g;
                bf[nt][0] = f2tf32(bs[base]);
                bf[nt][1] = f2tf32(bs[base+32]);
            }
            #pragma unroll
            for (int mt = 0; mt < 2; mt++)
                #pragma unroll
                for (int nt = 0; nt < NT; nt++) {
                    asm volatile(
                        "mma.sync.aligned.m16n8k8.row.col.f32.tf32.tf32.f32 "
                        "{%0,%1,%2,%3}, {%4,%5,%6,%7}, {%8,%9}, {%0,%1,%2,%3};\n"
                        : "+f"(acc[mt][nt][0]), "+f"(acc[mt][nt][1]),
                          "+f"(acc[mt][nt][2]), "+f"(acc[mt][nt][3])
                        : "r"(af[mt][0]), "r"(af[mt][1]), "r"(af[mt][2]), "r"(af[mt][3]),
                          "r"(bf[nt][0]), "r"(bf[nt][1]));
                }
        }
        __syncthreads();
    }

    // ---- epilogue (M, N are exact multiples of tile dims) ----
    #pragma unroll
    for (int mt = 0; mt < 2; mt++) {
        int r0 = by*BM + wm + mt*16 + g;
        #pragma unroll
        for (int nt = 0; nt < NT; nt++) {
            int c0 = bx*128 + wn + nt*8 + tg*2;
            float v0 = acc[mt][nt][0], v1 = acc[mt][nt][1];
            float v2 = acc[mt][nt][2], v3 = acc[mt][nt][3];
            if (RELU) { v0=fmaxf(v0,0.f); v1=fmaxf(v1,0.f); v2=fmaxf(v2,0.f); v3=fmaxf(v3,0.f); }
            *reinterpret_cast<float2*>(C + (long long)r0*ldc + c0)     = make_float2(v0, v1);
            *reinterpret_cast<float2*>(C + (long long)(r0+8)*ldc + c0) = make_float2(v2, v3);
        }
    }
}

// ---------------- legacy tf32 GEMM (precompute M / Wvo, handles transb) -----
#define GBM 128
#define GBN 128
#define GBK 16
#define SPAD 132

__global__ __launch_bounds__(256) void tf32gemm_kernel(
    const float* __restrict__ A, const float* __restrict__ B, float* __restrict__ C,
    int M, int N, int K, int lda, int ldb, int ldc, int transb, int relu)
{
    __shared__ unsigned As[GBK*SPAD];
    __shared__ unsigned Bs[GBK*SPAD];

    int tid = threadIdx.x;
    int lane = tid & 31;
    int warp = tid >> 5;
    int wm = (warp & 3) * 32;
    int wn = (warp >> 2) * 64;
    int bx = blockIdx.x, by = blockIdx.y;

    float acc[2][8][4];
    #pragma unroll
    for (int i=0;i<2;i++)
        #pragma unroll
        for (int j=0;j<8;j++)
            #pragma unroll
            for (int q=0;q<4;q++) acc[i][j][q] = 0.f;

    int g = lane >> 2;
    int tg = lane & 3;

    for (int k0 = 0; k0 < K; k0 += GBK) {
        #pragma unroll
        for (int i = 0; i < 8; i++) {
            int idx = tid + i*256;
            int k = idx & 15, m = idx >> 4;
            int gr = by*GBM + m, gc = k0 + k;
            float v = (gr < M && gc < K) ? A[(long long)gr*lda + gc] : 0.f;
            As[k*SPAD + m] = f2tf32(v);
        }
        #pragma unroll
        for (int i = 0; i < 8; i++) {
            int idx = tid + i*256;
            int k = idx >> 7, n = idx & 127;
            int gk = k0 + k, gn = bx*GBN + n;
            float v = 0.f;
            if (gk < K && gn < N)
                v = transb ? B[(long long)gn*ldb + gk] : B[(long long)gk*ldb + gn];
            Bs[k*SPAD + n] = f2tf32(v);
        }
        __syncthreads();

        #pragma unroll
        for (int ks = 0; ks < 2; ks++) {
            int kb = ks*8;
            unsigned af[2][4];
            #pragma unroll
            for (int mt = 0; mt < 2; mt++) {
                int r = wm + mt*16 + g;
                int c = kb + tg;
                af[mt][0] = As[c*SPAD + r];
                af[mt][1] = As[c*SPAD + r + 8];
                af[mt][2] = As[(c+4)*SPAD + r];
                af[mt][3] = As[(c+4)*SPAD + r + 8];
            }
            unsigned bf[8][2];
            #pragma unroll
            for (int nt = 0; nt < 8; nt++) {
                int col = wn + nt*8 + g;
                int kk = kb + tg;
                bf[nt][0] = Bs[kk*SPAD + col];
                bf[nt][1] = Bs[(kk+4)*SPAD + col];
            }
            #pragma unroll
            for (int mt = 0; mt < 2; mt++)
                #pragma unroll
                for (int nt = 0; nt < 8; nt++) {
                    asm volatile(
                        "mma.sync.aligned.m16n8k8.row.col.f32.tf32.tf32.f32 "
                        "{%0,%1,%2,%3}, {%4,%5,%6,%7}, {%8,%9}, {%0,%1,%2,%3};\n"
                        : "+f"(acc[mt][nt][0]), "+f"(acc[mt][nt][1]),
                          "+f"(acc[mt][nt][2]), "+f"(acc[mt][nt][3])
                        : "r"(af[mt][0]), "r"(af[mt][1]), "r"(af[mt][2]), "r"(af[mt][3]),
                          "r"(bf[nt][0]), "r"(bf[nt][1]));
                }
        }
        __syncthreads();
    }

    #pragma unroll
    for (int mt = 0; mt < 2; mt++) {
        int r0 = by*GBM + wm + mt*16 + g;
        #pragma unroll
        for (int nt = 0; nt < 8; nt++) {
            int c0 = bx*GBN + wn + nt*8 + tg*2;
            float v0 = acc[mt][nt][0], v1 = acc[mt][nt][1];
            float v2 = acc[mt][nt][2], v3 = acc[mt][nt][3];
            if (relu) { v0=fmaxf(v0,0.f); v1=fmaxf(v1,0.f); v2=fmaxf(v2,0.f); v3=fmaxf(v3,0.f); }
            if (r0 < M) {
                if (c0   < N) C[(long long)r0*ldc + c0  ] = v0;
                if (c0+1 < N) C[(long long)r0*ldc + c0+1] = v1;
            }
            if (r0+8 < M) {
                if (c0   < N) C[(long long)(r0+8)*ldc + c0  ] = v2;
                if (c0+1 < N) C[(long long)(r0+8)*ldc + c0+1] = v3;
            }
        }
    }
}

// ---------------- tokens ----------------
__global__ void tok_kernel(const float* __restrict__ pos_embed)
{
    int i = blockIdx.x;
    for (int d = threadIdx.x; d < DIMK; d += blockDim.x) {
        const float* hp = g_h3 + (long long)d*N3 + (long long)i*49;
        float s = 0.f;
        #pragma unroll 7
        for (int p = 0; p < 49; p++) {
            float v = hp[p];
            s += v;
            g_tok[((long long)i*50 + 1 + p)*DIMK + d] = v + pos_embed[(1+p)*DIMK + d];
        }
        g_tok[(long long)i*50*DIMK + d] = s*(1.f/49.f) + pos_embed[d];
    }
}

// ---------------- attention ----------------
__global__ void attn_kernel()
{
    int i = blockIdx.x;
    __shared__ float sS[DIMK];
    __shared__ float slog[64];
    const float* t = g_tok + (long long)i*50*DIMK;
    for (int d = threadIdx.x; d < DIMK; d += blockDim.x) sS[d] = g_S[i*DIMK + d];
    __syncthreads();

    int w = threadIdx.x >> 5, lane = threadIdx.x & 31;
    for (int j = w; j < 50; j += 8) {
        const float* tj = t + (long long)j*DIMK;
        float s = 0.f;
        for (int d = lane; d < DIMK; d += 32) s += sS[d]*tj[d];
        #pragma unroll
        for (int o = 16; o > 0; o >>= 1) s += __shfl_down_sync(0xffffffff, s, o);
        if (lane == 0) slog[j] = s * 0.03125f;
    }
    __syncthreads();
    if (threadIdx.x == 0) {
        float mx = slog[0];
        for (int j = 1; j < 50; j++) mx = fmaxf(mx, slog[j]);
        float sum = 0.f;
        for (int j = 0; j < 50; j++) { float e = expf(slog[j]-mx); slog[j]=e; sum+=e; }
        float inv = 1.f/sum;
        for (int j = 0; j < 50; j++) slog[j] *= inv;
    }
    __syncthreads();
    for (int d = threadIdx.x; d < DIMK; d += blockDim.x) {
        float c = 0.f;
        #pragma unroll 10
        for (int j = 0; j < 50; j++) c += slog[j]*t[(long long)j*DIMK + d];
        g_CTX[i*DIMK + d] = c;
    }
}

// ---------------- final EMA fuse ----------------
__global__ void fuse_kernel(const float* __restrict__ bdd,
                            const float* __restrict__ momentum,
                            float* __restrict__ out)
{
    int n = blockIdx.x;
    float mom = *momentum;
    const int order[6] = {2,0,1,5,3,4};
    for (int d = threadIdx.x; d < DIMK; d += blockDim.x) {
        float e = bdd[d];
        #pragma unroll
        for (int k = 0; k < 6; k++) {
            int c = order[k];
            int ii = n*NCC + c;
            if (g_valid[ii]) e = mom*e + (1.f - mom)*g_EMB[(long long)ii*DIMK + d];
        }
        out[n*DIMK + d] = e;
    }
}

// ---------------- launch ----------------
static inline float* sym(const void* s) {
    void* p = nullptr;
    cudaGetSymbolAddress(&p, s);
    return (float*)p;
}

extern "C" void kernel_launch(void* const* d_in, const int* in_sizes, int n_in,
                              void* d_out, int out_size)
{
    const float* camera_imgs = (const float*)d_in[0];
    const float* pred_boxes  = (const float*)d_in[1];
    const float* img_aug     = (const float*)d_in[2];
    const float* lidar_aug   = (const float*)d_in[3];
    const float* lidar2img   = (const float*)d_in[4];
    const float* momentum    = (const float*)d_in[5];
    const float* bdd         = (const float*)d_in[6];
    const float* theta_w     = (const float*)d_in[7];
    const float* theta_b     = (const float*)d_in[8];
    const float* conv1       = (const float*)d_in[9];
    const float* conv2       = (const float*)d_in[10];
    const float* conv3       = (const float*)d_in[11];
    const float* pos_embed   = (const float*)d_in[12];
    const float* wq          = (const float*)d_in[13];
    const float* wk          = (const float*)d_in[14];
    const float* wv          = (const float*)d_in[15];
    const float* wo          = (const float*)d_in[16];
    float* out = (float*)d_out;

    float* pcrops = sym(g_crops);
    float* ph1 = sym(g_h1);
    float* ph2 = sym(g_h2);
    float* ph3 = sym(g_h3);
    float* ptok = sym(g_tok);  float* pM  = sym(g_M);
    float* pWvo = sym(g_Wvo);  float* pS  = sym(g_S);
    float* pCTX = sym(g_CTX);  float* pEMB= sym(g_EMB);

    // precompute M = wq @ wk^T ; Wvo = wv @ wo
    {
        dim3 g(DIMK/GBN, DIMK/GBM);
        tf32gemm_kernel<<<g,256>>>(wq, wk, pM,  DIMK, DIMK, DIMK, DIMK, DIMK, DIMK, 1, 0);
        tf32gemm_kernel<<<g,256>>>(wv, wo, pWvo,DIMK, DIMK, DIMK, DIMK, DIMK, DIMK, 0, 0);
    }

    // projection / theta
    theta_kernel<<<2,192>>>(pred_boxes, lidar_aug, lidar2img, img_aug, theta_w, theta_b);

    // grid sample
    {
        long long total = (long long)NIMG*CROPS*CROPS;
        sample_kernel<<<(unsigned)((total+255)/256),256>>>(camera_imgs);
    }

    // conv1: implicit im2col from crops.  M=64, N=N1, K=147
    {
        dim3 g((unsigned)(N1/128), 1);
        pgemm<1, 64, true><<<g,256>>>(conv1, pcrops, ph1, 64, (int)N1, K1, K1, 0, (int)N1);
    }
    // conv2: implicit im2col from h1.    M=256, N=N2, K=576
    {
        dim3 g((unsigned)(N2/128), 2);
        pgemm<2, 128, true><<<g,256>>>(conv2, ph1, ph2, 256, (int)N2, K2, K2, 0, (int)N2);
    }
    // conv3: implicit im2col from h2.    M=1024, N=N3, K=2304
    {
        dim3 g((unsigned)(N3/128), 8);
        pgemm<3, 128, true><<<g,256>>>(conv3, ph2, ph3, 1024, (int)N3, K3, K3, 0, (int)N3);
    }

    // tokens (+ pos embed, cls mean)
    tok_kernel<<<NIMG,256>>>(pos_embed);

    // S = tok0 @ M   (A rows strided by 50*DIMK)
    {
        dim3 g(DIMK/128, NIMG/128);
        pgemm<0, 128, false><<<g,256>>>(ptok, pM, pS, NIMG, DIMK, DIMK, 50*DIMK, DIMK, DIMK);
    }

    // softmax + context
    attn_kernel<<<NIMG,256>>>();

    // EMB = CTX @ Wvo
    {
        dim3 g(DIMK/128, NIMG/128);
        pgemm<0, 128, false><<<g,256>>>(pCTX, pWvo, pEMB, NIMG, DIMK, DIMK, DIMK, DIMK, DIMK);
    }

    // EMA fuse -> out (64 x 1024)
    fuse_kernel<<<NBOX,256>>>(bdd, momentum, out);
}

// round 6
// speedup vs baseline: 1.1098x; 1.1098x over previous
#include <cuda_runtime.h>
#include <math.h>

// ---------------- problem constants ----------------
#define DIMK   1024
#define IMG_H  512
#define IMG_W  1408
#define CROPS  224
#define NCC    6
#define NBB    32
#define NBOX   64
#define NIMG   384
#define O1 56
#define O2 14
#define O3 7
#define N1 ((long long)NIMG*O1*O1)   // 1204224
#define N2 ((long long)NIMG*O2*O2)   // 75264
#define N3 ((long long)NIMG*O3*O3)   // 18816
#define K1 147
#define K2 576
#define K3 2304

// ---------------- scratch ----------------
__device__ float g_theta[NIMG*6];
__device__ int   g_valid[NIMG];
__device__ float g_crops[3LL*NIMG*CROPS*CROPS];
__device__ float g_h1[64LL*N1];
__device__ float g_h2[256LL*N2];
__device__ float g_h3[1024LL*N3];
__device__ float g_tok[(long long)NIMG*50*DIMK];
__device__ float g_M[DIMK*DIMK];
__device__ float g_Wvo[DIMK*DIMK];
__device__ float g_S[NIMG*DIMK];
__device__ float g_CTX[NIMG*DIMK];
__device__ float g_EMB[NIMG*DIMK];

// ---------------- theta / projection ----------------
__global__ void theta_kernel(const float* __restrict__ boxes, const float* __restrict__ la,
                             const float* __restrict__ l2i, const float* __restrict__ aug,
                             const float* __restrict__ thw, const float* __restrict__ thb)
{
    int t = blockIdx.x*blockDim.x + threadIdx.x;
    if (t >= NIMG) return;
    int c = t % NCC; int n = t / NCC; int b = n / NBB; int nb = n % NBB;
    const float* bx = boxes + (b*NBB + nb)*9;
    float r[4];
    #pragma unroll
    for (int i = 0; i < 4; i++) {
        float s = thb[i];
        #pragma unroll
        for (int j = 0; j < 9; j++) s += bx[j]*thw[i*9+j];
        r[i] = tanhf(s);
    }
    const float* L = la + b*16;
    float cx = bx[0]-L[3], cy = bx[1]-L[7], cz = bx[2]-L[11];
    float a00=L[0],a01=L[1],a02=L[2],a10=L[4],a11=L[5],a12=L[6],a20=L[8],a21=L[9],a22=L[10];
    float det = a00*(a11*a22-a12*a21) - a01*(a10*a22-a12*a20) + a02*(a10*a21-a11*a20);
    float id = 1.f/det;
    float x = ((a11*a22-a12*a21)*cx + (a02*a21-a01*a22)*cy + (a01*a12-a02*a11)*cz)*id;
    float y = ((a12*a20-a10*a22)*cx + (a00*a22-a02*a20)*cy + (a02*a10-a00*a12)*cz)*id;
    float z = ((a10*a21-a11*a20)*cx + (a01*a20-a00*a21)*cy + (a00*a11-a01*a10)*cz)*id;
    const float* P = l2i + (b*NCC + c)*16;
    float px = P[0]*x + P[1]*y + P[2]*z  + P[3];
    float py = P[4]*x + P[5]*y + P[6]*z  + P[7];
    float pz = P[8]*x + P[9]*y + P[10]*z + P[11];
    float zz = fminf(fmaxf(pz, 1e-5f), 100000.f);
    float qx = px/zz, qy = py/zz;
    const float* A = aug + (b*NCC + c)*16;
    float ux = A[0]*qx + A[1]*qy + A[2]*zz + A[3];
    float uy = A[4]*qx + A[5]*qy + A[6]*zz + A[7];
    int on = (uy < (float)IMG_H) && (uy >= 0.f) && (ux < (float)IMG_W) && (ux >= 0.f);
    g_theta[t*6+0]=r[0]; g_theta[t*6+1]=r[1]; g_theta[t*6+2]=ux/(float)IMG_W*2.f-1.f;
    g_theta[t*6+3]=r[2]; g_theta[t*6+4]=r[3]; g_theta[t*6+5]=uy/(float)IMG_H*2.f-1.f;
    g_valid[t] = on;
}

// ---------------- grid sample -> crops ----------------
__global__ void sample_kernel(const float* __restrict__ imgs)
{
    long long idx = (long long)blockIdx.x*blockDim.x + threadIdx.x;
    if (idx >= (long long)NIMG*CROPS*CROPS) return;
    int x = (int)(idx % CROPS);
    int y = (int)((idx / CROPS) % CROPS);
    int ii = (int)(idx / (CROPS*CROPS));
    int c = ii % NCC; int n = ii / NCC; int b = n / NBB;
    float t0 = g_theta[ii*6+0], t1 = g_theta[ii*6+1], t2 = g_theta[ii*6+2];
    float t3 = g_theta[ii*6+3], t4 = g_theta[ii*6+4], t5 = g_theta[ii*6+5];
    float gx = (2.f*x + 1.f)/(float)CROPS - 1.f;
    float gy = (2.f*y + 1.f)/(float)CROPS - 1.f;
    float g0 = gx*t0 + gy*t1 + t2;
    float g1 = gx*t3 + gy*t4 + t5;
    float ixf = ((g0 + 1.f)*(float)IMG_W - 1.f)*0.5f;
    float iyf = ((g1 + 1.f)*(float)IMG_H - 1.f)*0.5f;
    float x0 = floorf(ixf), y0 = floorf(iyf);
    float wx = ixf - x0, wy = iyf - y0;
    float x1 = x0 + 1.f, y1 = y0 + 1.f;
    bool vx0 = (x0 >= 0.f) && (x0 <= (float)(IMG_W-1));
    bool vx1 = (x1 >= 0.f) && (x1 <= (float)(IMG_W-1));
    bool vy0 = (y0 >= 0.f) && (y0 <= (float)(IMG_H-1));
    bool vy1 = (y1 >= 0.f) && (y1 <= (float)(IMG_H-1));
    int xi0 = (int)fminf(fmaxf(x0,0.f),(float)(IMG_W-1));
    int xi1 = (int)fminf(fmaxf(x1,0.f),(float)(IMG_W-1));
    int yi0 = (int)fminf(fmaxf(y0,0.f),(float)(IMG_H-1));
    int yi1 = (int)fminf(fmaxf(y1,0.f),(float)(IMG_H-1));
    float w00=(1.f-wx)*(1.f-wy), w01=wx*(1.f-wy), w10=(1.f-wx)*wy, w11=wx*wy;
    const float* base = imgs + (long long)(b*NCC + c)*3LL*IMG_H*IMG_W;
    #pragma unroll
    for (int ch = 0; ch < 3; ch++) {
        const float* im = base + (long long)ch*IMG_H*IMG_W;
        float v00 = (vx0&&vy0) ? im[yi0*IMG_W + xi0] : 0.f;
        float v01 = (vx1&&vy0) ? im[yi0*IMG_W + xi1] : 0.f;
        float v10 = (vx0&&vy1) ? im[yi1*IMG_W + xi0] : 0.f;
        float v11 = (vx1&&vy1) ? im[yi1*IMG_W + xi1] : 0.f;
        g_crops[((long long)(ch*NIMG + ii)*CROPS + y)*CROPS + x] =
            v00*w00 + v01*w01 + v10*w10 + v11*w11;
    }
}

// ---------------- helpers ----------------
__device__ __forceinline__ unsigned f2tf32(float f) {
    unsigned u;
    asm("cvt.rna.tf32.f32 %0, %1;" : "=r"(u) : "f"(f));
    return u;
}
// pack two f32 -> f16x2, lo = first arg
__device__ __forceinline__ unsigned packh2(float lo, float hi) {
    unsigned r;
    asm("cvt.rn.f16x2.f32 %0, %1, %2;" : "=r"(r) : "f"(hi), "f"(lo));
    return r;
}
__device__ __forceinline__ void cpasync4(unsigned dst, const float* src, bool pred) {
    asm volatile("cp.async.ca.shared.global [%0], [%1], 4, %2;\n"
        :: "r"(dst), "l"(src), "r"(pred ? 4 : 0) : "memory");
}
__device__ __forceinline__ void cpasync16(unsigned dst, const float* src) {
    asm volatile("cp.async.cg.shared.global [%0], [%1], 16;\n"
        :: "r"(dst), "l"(src) : "memory");
}
#define CP_COMMIT() asm volatile("cp.async.commit_group;\n" ::: "memory")
#define CP_WAIT1()  asm volatile("cp.async.wait_group 1;\n" ::: "memory")

// =====================================================================
// Pipelined implicit-GEMM, fp16 tensor cores (m16n8k16, fp32 accum).
// C[M][N] = A[M][K] * B(K,N);  B materialized on the fly per LOADER.
// Block tile BM x 128 x 16, 3-stage cp.async pipeline, 256 threads.
// smem fragment-native: addr(m,k)=(m>>3)*128+k*8+(m&7).
// LOADER: 0=dense B[k][n], 1=conv1 gather, 2=conv2 gather, 3=conv3 gather
// =====================================================================
template<int LOADER, int BM, bool RELU>
__global__ __launch_bounds__(256) void pgemm(
    const float* __restrict__ A, const float* __restrict__ B, float* __restrict__ C,
    int M, int N, int K, int lda, int ldb, int ldc)
{
    constexpr int ASTG = BM*16;
    __shared__ float As[3][ASTG];
    __shared__ float Bs[3][2048];

    const int tid = threadIdx.x;
    const int bx = blockIdx.x, by = blockIdx.y;

    const int nloc = tid & 127;
    const int ngl  = bx*128 + nloc;
    const int bdst0 = (nloc>>3)*128 + (nloc&7);
    const int krow0 = tid >> 7;

    long long cv_base = 0;  int cv_yb = 0, cv_xb = 0;
    if (LOADER == 1) {
        int img = ngl/3136; int pos = ngl - img*3136;
        int oy = pos/56, ox = pos - oy*56;
        cv_yb = oy*4 - 1; cv_xb = ox*4 - 1;
        cv_base = (long long)img*(CROPS*CROPS);
    } else if (LOADER == 2) {
        int img = ngl/196; int pos = ngl - img*196;
        int oy = pos/14, ox = pos - oy*14;
        cv_base = (long long)img*3136 + (long long)(oy*4)*56 + ox*4;
    } else if (LOADER == 3) {
        int img = ngl/49; int pos = ngl - img*49;
        int oy = pos/7, ox = pos - oy*7;
        cv_yb = oy*2; cv_xb = ox*2;
        cv_base = (long long)img*196;
    }

    unsigned sA0 = (unsigned)__cvta_generic_to_shared(&As[0][0]);
    unsigned sB0 = (unsigned)__cvta_generic_to_shared(&Bs[0][0]);

    auto load_stage = [&](int st, int k0) {
        unsigned sa = sA0 + (unsigned)(st*ASTG*4);
        unsigned sb = sB0 + (unsigned)(st*2048*4);
        #pragma unroll
        for (int i = 0; i < ASTG/256; i++) {
            int e = tid + i*256;
            int k = e & 15, m = e >> 4;
            int gc = k0 + k;
            const float* src = A + (long long)(by*BM + m)*lda + gc;
            unsigned dst = sa + (unsigned)(((m>>3)*128 + k*8 + (m&7))*4);
            cpasync4(dst, src, gc < K);
        }
        if (LOADER == 0) {
            #pragma unroll
            for (int i = 0; i < 2; i++) {
                int cch = tid + i*256;
                int k = cch >> 5; int n4 = (cch & 31)*4;
                const float* src = B + (long long)(k0 + k)*ldb + bx*128 + n4;
                unsigned dst = sb + (unsigned)((((n4>>3)*128) + k*8 + (n4&7))*4);
                cpasync16(dst, src);
            }
        } else {
            #pragma unroll
            for (int i = 0; i < 8; i++) {
                int krow = krow0 + 2*i;
                int k = k0 + krow;
                unsigned dst = sb + (unsigned)((bdst0 + krow*8)*4);
                if (LOADER == 1) {
                    int ch = k/49; int rr = k - ch*49;
                    int ky = rr/7, kx = rr - ky*7;
                    int iy = cv_yb + ky, ix = cv_xb + kx;
                    bool p = (k < K) && (iy >= 0) && (iy < CROPS) && (ix >= 0) && (ix < CROPS);
                    const float* src = B + ((long long)ch*NIMG*(CROPS*CROPS) + cv_base + (long long)iy*CROPS + ix);
                    cpasync4(dst, src, p);
                } else if (LOADER == 2) {
                    int ic = k/9; int rr = k - ic*9;
                    int ky = rr/3, kx = rr - ky*3;
                    const float* src = B + ((long long)ic*N1 + cv_base + ky*56 + kx);
                    cpasync4(dst, src, true);
                } else {
                    int ic = k/9; int rr = k - ic*9;
                    int ky = rr/3, kx = rr - ky*3;
                    int iy = cv_yb + ky, ix = cv_xb + kx;
                    bool p = (iy < 14) && (ix < 14);
                    const float* src = B + ((long long)ic*N2 + cv_base + iy*14 + ix);
                    cpasync4(dst, src, p);
                }
            }
        }
    };

    constexpr int WMC = BM/32;
    constexpr int WN  = 128/(8/WMC);
    constexpr int NT  = WN/8;
    const int lane = tid & 31, warp = tid >> 5;
    const int wm = (warp % WMC)*32;
    const int wn = (warp / WMC)*WN;
    const int g  = lane >> 2, tg = lane & 3;

    float acc[2][NT][4];
    #pragma unroll
    for (int i=0;i<2;i++)
        #pragma unroll
        for (int j=0;j<NT;j++)
            #pragma unroll
            for (int q=0;q<4;q++) acc[i][j][q] = 0.f;

    const int T = (K + 15)/16;

    load_stage(0, 0);  CP_COMMIT();
    load_stage(1, 16); CP_COMMIT();

    for (int kt = 0; kt < T; kt++) {
        CP_WAIT1();
        __syncthreads();
        int kn = kt + 2;
        if (kn < T) load_stage(kn % 3, kn*16);
        CP_COMMIT();

        const float* as = As[kt % 3];
        const float* bs = Bs[kt % 3];

        // fp16 fragments for one m16n8k16 step (k = 0..15 of this chunk)
        unsigned af[2][4];
        #pragma unroll
        for (int mt = 0; mt < 2; mt++) {
            int b1 = ((wm + mt*16)>>3)*128 + g;     // rows g
            int b2 = b1 + 128;                      // rows g+8
            int kA = 2*tg*8;                        // k = 2tg
            af[mt][0] = packh2(as[b1 + kA],      as[b1 + kA + 8]);
            af[mt][1] = packh2(as[b2 + kA],      as[b2 + kA + 8]);
            af[mt][2] = packh2(as[b1 + kA + 64], as[b1 + kA + 72]);   // k+8
            af[mt][3] = packh2(as[b2 + kA + 64], as[b2 + kA + 72]);
        }
        unsigned bf[NT][2];
        #pragma unroll
        for (int nt = 0; nt < NT; nt++) {
            int base = ((wn>>3) + nt)*128 + g;
            int kB = 2*tg*8;
            bf[nt][0] = packh2(bs[base + kB],      bs[base + kB + 8]);
            bf[nt][1] = packh2(bs[base + kB + 64], bs[base + kB + 72]);
        }
        #pragma unroll
        for (int mt = 0; mt < 2; mt++)
            #pragma unroll
            for (int nt = 0; nt < NT; nt++) {
                asm volatile(
                    "mma.sync.aligned.m16n8k16.row.col.f32.f16.f16.f32 "
                    "{%0,%1,%2,%3}, {%4,%5,%6,%7}, {%8,%9}, {%0,%1,%2,%3};\n"
                    : "+f"(acc[mt][nt][0]), "+f"(acc[mt][nt][1]),
                      "+f"(acc[mt][nt][2]), "+f"(acc[mt][nt][3])
                    : "r"(af[mt][0]), "r"(af[mt][1]), "r"(af[mt][2]), "r"(af[mt][3]),
                      "r"(bf[nt][0]), "r"(bf[nt][1]));
            }
        __syncthreads();
    }

    #pragma unroll
    for (int mt = 0; mt < 2; mt++) {
        int r0 = by*BM + wm + mt*16 + g;
        #pragma unroll
        for (int nt = 0; nt < NT; nt++) {
            int c0 = bx*128 + wn + nt*8 + tg*2;
            float v0 = acc[mt][nt][0], v1 = acc[mt][nt][1];
            float v2 = acc[mt][nt][2], v3 = acc[mt][nt][3];
            if (RELU) { v0=fmaxf(v0,0.f); v1=fmaxf(v1,0.f); v2=fmaxf(v2,0.f); v3=fmaxf(v3,0.f); }
            *reinterpret_cast<float2*>(C + (long long)r0*ldc + c0)     = make_float2(v0, v1);
            *reinterpret_cast<float2*>(C + (long long)(r0+8)*ldc + c0) = make_float2(v2, v3);
        }
    }
}

// ---------------- legacy tf32 GEMM (precompute M / Wvo, handles transb) -----
#define GBM 128
#define GBN 128
#define GBK 16
#define SPAD 132

__global__ __launch_bounds__(256) void tf32gemm_kernel(
    const float* __restrict__ A, const float* __restrict__ B, float* __restrict__ C,
    int M, int N, int K, int lda, int ldb, int ldc, int transb, int relu)
{
    __shared__ unsigned As[GBK*SPAD];
    __shared__ unsigned Bs[GBK*SPAD];

    int tid = threadIdx.x;
    int lane = tid & 31;
    int warp = tid >> 5;
    int wm = (warp & 3) * 32;
    int wn = (warp >> 2) * 64;
    int bx = blockIdx.x, by = blockIdx.y;

    float acc[2][8][4];
    #pragma unroll
    for (int i=0;i<2;i++)
        #pragma unroll
        for (int j=0;j<8;j++)
            #pragma unroll
            for (int q=0;q<4;q++) acc[i][j][q] = 0.f;

    int g = lane >> 2;
    int tg = lane & 3;

    for (int k0 = 0; k0 < K; k0 += GBK) {
        #pragma unroll
        for (int i = 0; i < 8; i++) {
            int idx = tid + i*256;
            int k = idx & 15, m = idx >> 4;
            int gr = by*GBM + m, gc = k0 + k;
            float v = (gr < M && gc < K) ? A[(long long)gr*lda + gc] : 0.f;
            As[k*SPAD + m] = f2tf32(v);
        }
        #pragma unroll
        for (int i = 0; i < 8; i++) {
            int idx = tid + i*256;
            int k = idx >> 7, n = idx & 127;
            int gk = k0 + k, gn = bx*GBN + n;
            float v = 0.f;
            if (gk < K && gn < N)
                v = transb ? B[(long long)gn*ldb + gk] : B[(long long)gk*ldb + gn];
            Bs[k*SPAD + n] = f2tf32(v);
        }
        __syncthreads();

        #pragma unroll
        for (int ks = 0; ks < 2; ks++) {
            int kb = ks*8;
            unsigned af[2][4];
            #pragma unroll
            for (int mt = 0; mt < 2; mt++) {
                int r = wm + mt*16 + g;
                int c = kb + tg;
                af[mt][0] = As[c*SPAD + r];
                af[mt][1] = As[c*SPAD + r + 8];
                af[mt][2] = As[(c+4)*SPAD + r];
                af[mt][3] = As[(c+4)*SPAD + r + 8];
            }
            unsigned bf[8][2];
            #pragma unroll
            for (int nt = 0; nt < 8; nt++) {
                int col = wn + nt*8 + g;
                int kk = kb + tg;
                bf[nt][0] = Bs[kk*SPAD + col];
                bf[nt][1] = Bs[(kk+4)*SPAD + col];
            }
            #pragma unroll
            for (int mt = 0; mt < 2; mt++)
                #pragma unroll
                for (int nt = 0; nt < 8; nt++) {
                    asm volatile(
                        "mma.sync.aligned.m16n8k8.row.col.f32.tf32.tf32.f32 "
                        "{%0,%1,%2,%3}, {%4,%5,%6,%7}, {%8,%9}, {%0,%1,%2,%3};\n"
                        : "+f"(acc[mt][nt][0]), "+f"(acc[mt][nt][1]),
                          "+f"(acc[mt][nt][2]), "+f"(acc[mt][nt][3])
                        : "r"(af[mt][0]), "r"(af[mt][1]), "r"(af[mt][2]), "r"(af[mt][3]),
                          "r"(bf[nt][0]), "r"(bf[nt][1]));
                }
        }
        __syncthreads();
    }

    #pragma unroll
    for (int mt = 0; mt < 2; mt++) {
        int r0 = by*GBM + wm + mt*16 + g;
        #pragma unroll
        for (int nt = 0; nt < 8; nt++) {
            int c0 = bx*GBN + wn + nt*8 + tg*2;
            float v0 = acc[mt][nt][0], v1 = acc[mt][nt][1];
            float v2 = acc[mt][nt][2], v3 = acc[mt][nt][3];
            if (relu) { v0=fmaxf(v0,0.f); v1=fmaxf(v1,0.f); v2=fmaxf(v2,0.f); v3=fmaxf(v3,0.f); }
            if (r0 < M) {
                if (c0   < N) C[(long long)r0*ldc + c0  ] = v0;
                if (c0+1 < N) C[(long long)r0*ldc + c0+1] = v1;
            }
            if (r0+8 < M) {
                if (c0   < N) C[(long long)(r0+8)*ldc + c0  ] = v2;
                if (c0+1 < N) C[(long long)(r0+8)*ldc + c0+1] = v3;
            }
        }
    }
}

// ---------------- tokens ----------------
__global__ void tok_kernel(const float* __restrict__ pos_embed)
{
    int i = blockIdx.x;
    for (int d = threadIdx.x; d < DIMK; d += blockDim.x) {
        const float* hp = g_h3 + (long long)d*N3 + (long long)i*49;
        float s = 0.f;
        #pragma unroll 7
        for (int p = 0; p < 49; p++) {
            float v = hp[p];
            s += v;
            g_tok[((long long)i*50 + 1 + p)*DIMK + d] = v + pos_embed[(1+p)*DIMK + d];
        }
        g_tok[(long long)i*50*DIMK + d] = s*(1.f/49.f) + pos_embed[d];
    }
}

// ---------------- attention ----------------
__global__ void attn_kernel()
{
    int i = blockIdx.x;
    __shared__ float sS[DIMK];
    __shared__ float slog[64];
    const float* t = g_tok + (long long)i*50*DIMK;
    for (int d = threadIdx.x; d < DIMK; d += blockDim.x) sS[d] = g_S[i*DIMK + d];
    __syncthreads();
    int w = threadIdx.x >> 5, lane = threadIdx.x & 31;
    for (int j = w; j < 50; j += 8) {
        const float* tj = t + (long long)j*DIMK;
        float s = 0.f;
        for (int d = lane; d < DIMK; d += 32) s += sS[d]*tj[d];
        #pragma unroll
        for (int o = 16; o > 0; o >>= 1) s += __shfl_down_sync(0xffffffff, s, o);
        if (lane == 0) slog[j] = s * 0.03125f;
    }
    __syncthreads();
    if (threadIdx.x == 0) {
        float mx = slog[0];
        for (int j = 1; j < 50; j++) mx = fmaxf(mx, slog[j]);
        float sum = 0.f;
        for (int j = 0; j < 50; j++) { float e = expf(slog[j]-mx); slog[j]=e; sum+=e; }
        float inv = 1.f/sum;
        for (int j = 0; j < 50; j++) slog[j] *= inv;
    }
    __syncthreads();
    for (int d = threadIdx.x; d < DIMK; d += blockDim.x) {
        float c = 0.f;
        #pragma unroll 10
        for (int j = 0; j < 50; j++) c += slog[j]*t[(long long)j*DIMK + d];
        g_CTX[i*DIMK + d] = c;
    }
}

// ---------------- final EMA fuse ----------------
__global__ void fuse_kernel(const float* __restrict__ bdd,
                            const float* __restrict__ momentum,
                            float* __restrict__ out)
{
    int n = blockIdx.x;
    float mom = *momentum;
    const int order[6] = {2,0,1,5,3,4};
    for (int d = threadIdx.x; d < DIMK; d += blockDim.x) {
        float e = bdd[d];
        #pragma unroll
        for (int k = 0; k < 6; k++) {
            int c = order[k];
            int ii = n*NCC + c;
            if (g_valid[ii]) e = mom*e + (1.f - mom)*g_EMB[(long long)ii*DIMK + d];
        }
        out[n*DIMK + d] = e;
    }
}

// ---------------- launch ----------------
static inline float* sym(const void* s) {
    void* p = nullptr; cudaGetSymbolAddress(&p, s); return (float*)p;
}

extern "C" void kernel_launch(void* const* d_in, const int* in_sizes, int n_in,
                              void* d_out, int out_size)
{
    const float* camera_imgs = (const float*)d_in[0];
    const float* pred_boxes  = (const float*)d_in[1];
    const float* img_aug     = (const float*)d_in[2];
    const float* lidar_aug   = (const float*)d_in[3];
    const float* lidar2img   = (const float*)d_in[4];
    const float* momentum    = (const float*)d_in[5];
    const float* bdd         = (const float*)d_in[6];
    const float* theta_w     = (const float*)d_in[7];
    const float* theta_b     = (const float*)d_in[8];
    const float* conv1       = (const float*)d_in[9];
    const float* conv2       = (const float*)d_in[10];
    const float* conv3       = (const float*)d_in[11];
    const float* pos_embed   = (const float*)d_in[12];
    const float* wq          = (const float*)d_in[13];
    const float* wk          = (const float*)d_in[14];
    const float* wv          = (const float*)d_in[15];
    const float* wo          = (const float*)d_in[16];
    float* out = (float*)d_out;

    float* pcrops = sym(g_crops);
    float* ph1 = sym(g_h1);   float* ph2 = sym(g_h2);  float* ph3 = sym(g_h3);
    float* ptok = sym(g_tok); float* pM  = sym(g_M);   float* pWvo = sym(g_Wvo);
    float* pS  = sym(g_S);    float* pCTX = sym(g_CTX); float* pEMB = sym(g_EMB);

    // precompute M = wq @ wk^T ; Wvo = wv @ wo (tf32)
    {
        dim3 g(DIMK/GBN, DIMK/GBM);
        tf32gemm_kernel<<<g,256>>>(wq, wk, pM,  DIMK, DIMK, DIMK, DIMK, DIMK, DIMK, 1, 0);
        tf32gemm_kernel<<<g,256>>>(wv, wo, pWvo,DIMK, DIMK, DIMK, DIMK, DIMK, DIMK, 0, 0);
    }

    theta_kernel<<<2,192>>>(pred_boxes, lidar_aug, lidar2img, img_aug, theta_w, theta_b);
    {
        long long total = (long long)NIMG*CROPS*CROPS;
        sample_kernel<<<(unsigned)((total+255)/256),256>>>(camera_imgs);
    }

    // conv1: implicit im2col from crops.  M=64, N=N1, K=147
    pgemm<1, 64, true><<<dim3((unsigned)(N1/128),1),256>>>(conv1, pcrops, ph1, 64, (int)N1, K1, K1, 0, (int)N1);
    // conv2: implicit im2col from h1.     M=256, N=N2, K=576
    pgemm<2, 128, true><<<dim3((unsigned)(N2/128),2),256>>>(conv2, ph1, ph2, 256, (int)N2, K2, K2, 0, (int)N2);
    // conv3: implicit im2col from h2.     M=1024, N=N3, K=2304
    pgemm<3, 128, true><<<dim3((unsigned)(N3/128),8),256>>>(conv3, ph2, ph3, 1024, (int)N3, K3, K3, 0, (int)N3);

    tok_kernel<<<NIMG,256>>>(pos_embed);

    // S = tok0 @ M  (A rows strided by 50*DIMK)
    pgemm<0, 128, false><<<dim3(DIMK/128, NIMG/128),256>>>(ptok, pM, pS, NIMG, DIMK, DIMK, 50*DIMK, DIMK, DIMK);

    attn_kernel<<<NIMG,256>>>();

    // EMB = CTX @ Wvo
    pgemm<0, 128, false><<<dim3(DIMK/128, NIMG/128),256>>>(pCTX, pWvo, pEMB, NIMG, DIMK, DIMK, DIMK, DIMK, DIMK);

    fuse_kernel<<<NBOX,256>>>(bdd, momentum, out);
}

// round 7
// speedup vs baseline: 1.7160x; 1.5462x over previous
#include <cuda_runtime.h>
#include <cuda_fp16.h>
#include <math.h>

#define DIMK   1024
#define IMG_H  512
#define IMG_W  1408
#define CROPS  224
#define NCC    6
#define NBB    32
#define NBOX   64
#define NIMG   384
#define O1 56
#define O2 14
#define O3 7
#define N1 ((long long)NIMG*O1*O1)   // 1204224
#define N2 ((long long)NIMG*O2*O2)   // 75264
#define N3 ((long long)NIMG*O3*O3)   // 18816
#define K1 147
#define K2 576
#define K3 2304

// ---------------- scratch ----------------
__device__ float  g_theta[NIMG*6];
__device__ int    g_valid[NIMG];
__device__ __half g_cropsh[3LL*NIMG*CROPS*CROPS];   // [ch][img][y][x]
__device__ __half g_h1h[64LL*N1];
__device__ __half g_h2h[256LL*N2];
__device__ float  g_h3[1024LL*N3];
__device__ float  g_tok[(long long)NIMG*50*DIMK];
__device__ float  g_S[NIMG*DIMK];
__device__ float  g_EMB[NIMG*DIMK];
// packed (u32 = 2 halves along k)
__device__ unsigned g_wqp[512*1024], g_wvp[512*1024];
__device__ unsigned g_wkTp[512*1024], g_wop[512*1024];
__device__ unsigned g_Mp[512*1024], g_Wvop[512*1024];
__device__ unsigned g_w1p[64*80];
__device__ unsigned g_w2p[256*288];
__device__ unsigned g_w3p[1024*1152];
__device__ unsigned g_tok0p[384*512];
__device__ unsigned g_CTXp[384*512];

// ---------------- pack kernels ----------------
// A packed: u32 idx = ((mblk*NCH + chunk)*16 + kp)*BM + mloc   (NCH = Kpad/32)
__global__ void packA_kernel(const float* __restrict__ src, unsigned* __restrict__ dst,
                             int Ms, int Ks, int BMp, int Kpad, long long total)
{
    long long i = (long long)blockIdx.x*256 + threadIdx.x;
    if (i >= total) return;
    int NCH = Kpad/32;
    int mloc = (int)(i % BMp); long long r = i / BMp;
    int kp = (int)(r % 16); r /= 16;
    int chunk = (int)(r % NCH); int mblk = (int)(r / NCH);
    int m = mblk*BMp + mloc, k = chunk*32 + kp*2;
    float v0 = (m < Ms && k   < Ks) ? src[(long long)m*Ks + k]   : 0.f;
    float v1 = (m < Ms && k+1 < Ks) ? src[(long long)m*Ks + k+1] : 0.f;
    __half2 h = __floats2half2_rn(v0, v1);
    dst[i] = *reinterpret_cast<unsigned*>(&h);
}
// dense B packed: u32 idx = (chunk*16+kp)*N + n ; B[k][n] = src[k][n] (or src[n][k] if T)
__global__ void packBd_kernel(const float* __restrict__ src, unsigned* __restrict__ dst,
                              int Kd, int Nd, int transb)
{
    long long i = (long long)blockIdx.x*256 + threadIdx.x;
    if (i >= (long long)(Kd/2)*Nd) return;
    int n = (int)(i % Nd); long long r = i / Nd;
    int kp = (int)(r % 16); int chunk = (int)(r / 16);
    int k = chunk*32 + kp*2;
    float v0 = transb ? src[(long long)n*Kd + k]   : src[(long long)k*Nd + n];
    float v1 = transb ? src[(long long)n*Kd + k+1] : src[(long long)(k+1)*Nd + n];
    __half2 h = __floats2half2_rn(v0, v1);
    dst[i] = *reinterpret_cast<unsigned*>(&h);
}

// ---------------- theta ----------------
__global__ void theta_kernel(const float* __restrict__ boxes, const float* __restrict__ la,
                             const float* __restrict__ l2i, const float* __restrict__ aug,
                             const float* __restrict__ thw, const float* __restrict__ thb)
{
    int t = blockIdx.x*blockDim.x + threadIdx.x;
    if (t >= NIMG) return;
    int c = t % NCC; int n = t / NCC; int b = n / NBB; int nb = n % NBB;
    const float* bx = boxes + (b*NBB + nb)*9;
    float r[4];
    #pragma unroll
    for (int i = 0; i < 4; i++) {
        float s = thb[i];
        #pragma unroll
        for (int j = 0; j < 9; j++) s += bx[j]*thw[i*9+j];
        r[i] = tanhf(s);
    }
    const float* L = la + b*16;
    float cx = bx[0]-L[3], cy = bx[1]-L[7], cz = bx[2]-L[11];
    float a00=L[0],a01=L[1],a02=L[2],a10=L[4],a11=L[5],a12=L[6],a20=L[8],a21=L[9],a22=L[10];
    float det = a00*(a11*a22-a12*a21) - a01*(a10*a22-a12*a20) + a02*(a10*a21-a11*a20);
    float id = 1.f/det;
    float x = ((a11*a22-a12*a21)*cx + (a02*a21-a01*a22)*cy + (a01*a12-a02*a11)*cz)*id;
    float y = ((a12*a20-a10*a22)*cx + (a00*a22-a02*a20)*cy + (a02*a10-a00*a12)*cz)*id;
    float z = ((a10*a21-a11*a20)*cx + (a01*a20-a00*a21)*cy + (a00*a11-a01*a10)*cz)*id;
    const float* P = l2i + (b*NCC + c)*16;
    float px = P[0]*x + P[1]*y + P[2]*z  + P[3];
    float py = P[4]*x + P[5]*y + P[6]*z  + P[7];
    float pz = P[8]*x + P[9]*y + P[10]*z + P[11];
    float zz = fminf(fmaxf(pz, 1e-5f), 100000.f);
    float qx = px/zz, qy = py/zz;
    const float* A = aug + (b*NCC + c)*16;
    float ux = A[0]*qx + A[1]*qy + A[2]*zz + A[3];
    float uy = A[4]*qx + A[5]*qy + A[6]*zz + A[7];
    int on = (uy < (float)IMG_H) && (uy >= 0.f) && (ux < (float)IMG_W) && (ux >= 0.f);
    g_theta[t*6+0]=r[0]; g_theta[t*6+1]=r[1]; g_theta[t*6+2]=ux/(float)IMG_W*2.f-1.f;
    g_theta[t*6+3]=r[2]; g_theta[t*6+4]=r[3]; g_theta[t*6+5]=uy/(float)IMG_H*2.f-1.f;
    g_valid[t] = on;
}

// ---------------- grid sample -> half crops ----------------
__global__ void sample_kernel(const float* __restrict__ imgs)
{
    long long idx = (long long)blockIdx.x*blockDim.x + threadIdx.x;
    if (idx >= (long long)NIMG*CROPS*CROPS) return;
    int x = (int)(idx % CROPS);
    int y = (int)((idx / CROPS) % CROPS);
    int ii = (int)(idx / (CROPS*CROPS));
    int c = ii % NCC; int n = ii / NCC; int b = n / NBB;
    float t0 = g_theta[ii*6+0], t1 = g_theta[ii*6+1], t2 = g_theta[ii*6+2];
    float t3 = g_theta[ii*6+3], t4 = g_theta[ii*6+4], t5 = g_theta[ii*6+5];
    float gx = (2.f*x + 1.f)/(float)CROPS - 1.f;
    float gy = (2.f*y + 1.f)/(float)CROPS - 1.f;
    float g0 = gx*t0 + gy*t1 + t2;
    float g1 = gx*t3 + gy*t4 + t5;
    float ixf = ((g0 + 1.f)*(float)IMG_W - 1.f)*0.5f;
    float iyf = ((g1 + 1.f)*(float)IMG_H - 1.f)*0.5f;
    float x0 = floorf(ixf), y0 = floorf(iyf);
    float wx = ixf - x0, wy = iyf - y0;
    float x1 = x0 + 1.f, y1 = y0 + 1.f;
    bool vx0 = (x0 >= 0.f) && (x0 <= (float)(IMG_W-1));
    bool vx1 = (x1 >= 0.f) && (x1 <= (float)(IMG_W-1));
    bool vy0 = (y0 >= 0.f) && (y0 <= (float)(IMG_H-1));
    bool vy1 = (y1 >= 0.f) && (y1 <= (float)(IMG_H-1));
    int xi0 = (int)fminf(fmaxf(x0,0.f),(float)(IMG_W-1));
    int xi1 = (int)fminf(fmaxf(x1,0.f),(float)(IMG_W-1));
    int yi0 = (int)fminf(fmaxf(y0,0.f),(float)(IMG_H-1));
    int yi1 = (int)fminf(fmaxf(y1,0.f),(float)(IMG_H-1));
    float w00=(1.f-wx)*(1.f-wy), w01=wx*(1.f-wy), w10=(1.f-wx)*wy, w11=wx*wy;
    const float* base = imgs + (long long)(b*NCC + c)*3LL*IMG_H*IMG_W;
    #pragma unroll
    for (int ch = 0; ch < 3; ch++) {
        const float* im = base + (long long)ch*IMG_H*IMG_W;
        float v00 = (vx0&&vy0) ? im[yi0*IMG_W + xi0] : 0.f;
        float v01 = (vx1&&vy0) ? im[yi0*IMG_W + xi1] : 0.f;
        float v10 = (vx0&&vy1) ? im[yi1*IMG_W + xi0] : 0.f;
        float v11 = (vx1&&vy1) ? im[yi1*IMG_W + xi1] : 0.f;
        g_cropsh[((long long)(ch*NIMG + ii)*CROPS + y)*CROPS + x] =
            __float2half_rn(v00*w00 + v01*w01 + v10*w10 + v11*w11);
    }
}

// ---------------- cp.async helpers ----------------
__device__ __forceinline__ void cpasync16(unsigned dst, const void* src) {
    asm volatile("cp.async.cg.shared.global [%0], [%1], 16;\n"
        :: "r"(dst), "l"(src) : "memory");
}
#define CP_COMMIT() asm volatile("cp.async.commit_group;\n" ::: "memory")
#define CP_WAIT1()  asm volatile("cp.async.wait_group 1;\n" ::: "memory")

// =====================================================================
// Half-native pipelined GEMM, m16n8k16 fp16 MMA, fp32 accum.
// A: packed u32 [(mblk*NCH+chunk)*16+kp]*BM + mloc  (half2 k-pairs)
// B: LOADER 0 = dense packed u32 (chunk*16+kp)*N + n (cp.async)
//    LOADER 1/2/3 = implicit-im2col gather from __half source (reg-staged)
// CW: 0 = float C, 1 = half C, 2 = packed-dense-B C (for M/Wvo)
// =====================================================================
template<int LOADER, int BM, bool RELU, int CW>
__global__ __launch_bounds__(256) void hgemm(
    const unsigned* __restrict__ A, const void* __restrict__ Bp, void* __restrict__ Cp,
    int Kpad, int KR, int N, int ldc)
{
    constexpr int SROW = BM + 8;            // u32 stride (SROW%32==8 -> conflict-free)
    constexpr int ASZ  = 16*SROW;
    constexpr int BSZ  = 16*136;
    extern __shared__ unsigned smemU[];

    const int tid = threadIdx.x;
    const int bx = blockIdx.x, by = blockIdx.y;
    const int lane = tid & 31, warp = tid >> 5;
    const int g = lane >> 2, tg = lane & 3;
    constexpr int WMC = BM/32;
    constexpr int WN  = 128/(8/WMC);
    constexpr int NT  = WN/8;
    const int wm = (warp % WMC)*32;
    const int wn = (warp / WMC)*WN;

    const int NCH = Kpad/32;
    const int T = NCH;

    // conv gather context
    const int nloc = tid & 127;
    const int ngl  = bx*128 + nloc;
    const int hsel = tid >> 7;               // kp 0-7 or 8-15
    const __half* Bh = (const __half*)Bp;
    const unsigned* Bu = (const unsigned*)Bp;
    long long cv_base = 0; int cv_yb = 0, cv_xb = 0;
    if (LOADER == 1) {
        int img = ngl/3136, pos = ngl - img*3136;
        int oy = pos/56, ox = pos - oy*56;
        cv_yb = oy*4 - 1; cv_xb = ox*4 - 1;
        cv_base = (long long)img*(CROPS*CROPS);
    } else if (LOADER == 2) {
        int img = ngl/196, pos = ngl - img*196;
        int oy = pos/14, ox = pos - oy*14;
        cv_base = (long long)img*3136 + (long long)(oy*4)*56 + ox*4;
    } else if (LOADER == 3) {
        int img = ngl/49, pos = ngl - img*49;
        int oy = pos/7, ox = pos - oy*7;
        cv_yb = oy*2; cv_xb = ox*2;
        cv_base = (long long)img*196;
    }

    unsigned sbase = (unsigned)__cvta_generic_to_shared(smemU);

    auto fetch = [&](int kg) -> __half {
        __half v = __ushort_as_half((unsigned short)0);
        if (LOADER == 1) {
            int ch = kg/49, rr = kg - ch*49;
            int ky = rr/7, kx = rr - ky*7;
            int iy = cv_yb + ky, ix = cv_xb + kx;
            bool p = (kg < KR) && iy >= 0 && iy < CROPS && ix >= 0 && ix < CROPS;
            if (p) v = Bh[(long long)ch*(NIMG*(long long)(CROPS*CROPS)) + cv_base + (long long)iy*CROPS + ix];
        } else if (LOADER == 2) {
            int ic = kg/9, rr = kg - ic*9;
            int ky = rr/3, kx = rr - ky*3;
            v = Bh[(long long)ic*N1 + cv_base + ky*56 + kx];
        } else if (LOADER == 3) {
            int ic = kg/9, rr = kg - ic*9;
            int ky = rr/3, kx = rr - ky*3;
            int iy = cv_yb + ky, ix = cv_xb + kx;
            if (iy < 14 && ix < 14) v = Bh[(long long)ic*N2 + cv_base + iy*14 + ix];
        }
        return v;
    };

    unsigned Breg[8];
    auto gatherB = [&](int chunk) {
        #pragma unroll
        for (int j = 0; j < 8; j++) {
            int kp = hsel*8 + j;
            int kg = chunk*32 + kp*2;
            __half v0 = fetch(kg), v1 = fetch(kg+1);
            Breg[j] = ((unsigned)__half_as_ushort(v1) << 16) | (unsigned)__half_as_ushort(v0);
        }
    };
    auto storeB = [&](int st) {
        unsigned* sB = smemU + st*(ASZ+BSZ) + ASZ;
        #pragma unroll
        for (int j = 0; j < 8; j++)
            sB[(hsel*8 + j)*136 + nloc] = Breg[j];
    };
    auto loadA_cp = [&](int st, int chunk) {
        unsigned sa = sbase + (unsigned)(st*(ASZ+BSZ)*4);
        constexpr int perkp = BM/4;
        constexpr int NTR = 16*perkp;       // 16B transfers
        #pragma unroll
        for (int i = 0; i < NTR/256; i++) {
            int e = tid + i*256;
            int kp = e / perkp, mq = (e % perkp)*4;
            const unsigned* src = A + ((long long)(by*NCH + chunk)*16 + kp)*BM + mq;
            cpasync16(sa + (unsigned)((kp*SROW + mq)*4), src);
        }
    };
    auto loadB_cp = [&](int st, int chunk) {   // LOADER 0 only
        unsigned sb = sbase + (unsigned)((st*(ASZ+BSZ) + ASZ)*4);
        #pragma unroll
        for (int i = 0; i < 2; i++) {
            int e = tid + i*256;
            int kp = e >> 5, nq = (e & 31)*4;
            const unsigned* src = Bu + (long long)(chunk*16 + kp)*N + bx*128 + nq;
            cpasync16(sb + (unsigned)((kp*136 + nq)*4), src);
        }
    };

    float acc[2][NT][4];
    #pragma unroll
    for (int i=0;i<2;i++)
        #pragma unroll
        for (int j=0;j<NT;j++)
            #pragma unroll
            for (int q=0;q<4;q++) acc[i][j][q] = 0.f;

    // prologue
    if (LOADER == 0) {
        loadA_cp(0,0); loadB_cp(0,0); CP_COMMIT();
        loadA_cp(1,1); loadB_cp(1,1); CP_COMMIT();
    } else {
        gatherB(0); storeB(0);
        gatherB(1);
        loadA_cp(0,0); CP_COMMIT();
        loadA_cp(1,1); CP_COMMIT();
    }

    for (int kt = 0; kt < T; kt++) {
        CP_WAIT1();
        __syncthreads();
        int kn = kt + 2;
        if (kn < T) {
            int stn = kn % 3;
            loadA_cp(stn, kn);
            if (LOADER == 0) loadB_cp(stn, kn);
        }
        CP_COMMIT();

        int st = kt % 3;
        const unsigned* sA = smemU + st*(ASZ+BSZ);
        const unsigned* sB = sA + ASZ;
        #pragma unroll
        for (int s = 0; s < 2; s++) {
            int kb = s*8;
            unsigned af[2][4];
            #pragma unroll
            for (int mt = 0; mt < 2; mt++) {
                int r1 = wm + mt*16 + g;
                af[mt][0] = sA[(kb+tg)*SROW + r1];
                af[mt][1] = sA[(kb+tg)*SROW + r1 + 8];
                af[mt][2] = sA[(kb+tg+4)*SROW + r1];
                af[mt][3] = sA[(kb+tg+4)*SROW + r1 + 8];
            }
            unsigned bf[NT][2];
            #pragma unroll
            for (int nt = 0; nt < NT; nt++) {
                int cc = wn + nt*8 + g;
                bf[nt][0] = sB[(kb+tg)*136 + cc];
                bf[nt][1] = sB[(kb+tg+4)*136 + cc];
            }
            #pragma unroll
            for (int mt = 0; mt < 2; mt++)
                #pragma unroll
                for (int nt = 0; nt < NT; nt++) {
                    asm volatile(
                        "mma.sync.aligned.m16n8k16.row.col.f32.f16.f16.f32 "
                        "{%0,%1,%2,%3}, {%4,%5,%6,%7}, {%8,%9}, {%0,%1,%2,%3};\n"
                        : "+f"(acc[mt][nt][0]), "+f"(acc[mt][nt][1]),
                          "+f"(acc[mt][nt][2]), "+f"(acc[mt][nt][3])
                        : "r"(af[mt][0]), "r"(af[mt][1]), "r"(af[mt][2]), "r"(af[mt][3]),
                          "r"(bf[nt][0]), "r"(bf[nt][1]));
                }
        }
        if (LOADER != 0) {
            if (kt+1 < T) storeB((kt+1) % 3);
            if (kt+2 < T) gatherB(kt+2);
        }
    }

    // epilogue
    #pragma unroll
    for (int mt = 0; mt < 2; mt++) {
        int r0 = by*BM + wm + mt*16 + g;
        #pragma unroll
        for (int nt = 0; nt < NT; nt++) {
            int c0 = bx*128 + wn + nt*8 + tg*2;
            float v0 = acc[mt][nt][0], v1 = acc[mt][nt][1];
            float v2 = acc[mt][nt][2], v3 = acc[mt][nt][3];
            if (RELU) { v0=fmaxf(v0,0.f); v1=fmaxf(v1,0.f); v2=fmaxf(v2,0.f); v3=fmaxf(v3,0.f); }
            if (CW == 0) {
                float* C = (float*)Cp;
                *reinterpret_cast<float2*>(C + (long long)r0*ldc + c0)     = make_float2(v0, v1);
                *reinterpret_cast<float2*>(C + (long long)(r0+8)*ldc + c0) = make_float2(v2, v3);
            } else if (CW == 1) {
                __half* C = (__half*)Cp;
                __half2 h0 = __floats2half2_rn(v0, v1);
                __half2 h1 = __floats2half2_rn(v2, v3);
                *reinterpret_cast<__half2*>(C + (long long)r0*ldc + c0)     = h0;
                *reinterpret_cast<__half2*>(C + (long long)(r0+8)*ldc + c0) = h1;
            } else {
                __half* C = (__half*)Cp;
                auto st1 = [&](int r, int c, float v) {
                    long long idx = ((long long)((r>>5)*16 + ((r>>1)&15))*N + c)*2 + (r&1);
                    C[idx] = __float2half_rn(v);
                };
                st1(r0,   c0,   v0); st1(r0,   c0+1, v1);
                st1(r0+8, c0,   v2); st1(r0+8, c0+1, v3);
            }
        }
    }
}

// ---------------- tokens (float for attn + packed cls for S GEMM) ----------
__global__ void tok_kernel(const float* __restrict__ pos_embed)
{
    int i = blockIdx.x;
    int mblk = i >> 7, mloc = i & 127;
    __half* tp = (__half*)g_tok0p;
    for (int d = threadIdx.x; d < DIMK; d += blockDim.x) {
        const float* hp = g_h3 + (long long)d*N3 + (long long)i*49;
        float s = 0.f;
        #pragma unroll 7
        for (int p = 0; p < 49; p++) {
            float v = hp[p];
            s += v;
            g_tok[((long long)i*50 + 1 + p)*DIMK + d] = v + pos_embed[(1+p)*DIMK + d];
        }
        float t0 = s*(1.f/49.f) + pos_embed[d];
        g_tok[(long long)i*50*DIMK + d] = t0;
        int chunk = d >> 5, kp = (d & 31) >> 1;
        tp[(((long long)(mblk*32 + chunk)*16 + kp)*128 + mloc)*2 + (d&1)] = __float2half_rn(t0);
    }
}

// ---------------- attention ----------------
__global__ void attn_kernel()
{
    int i = blockIdx.x;
    __shared__ float sS[DIMK];
    __shared__ float slog[64];
    const float* t = g_tok + (long long)i*50*DIMK;
    for (int d = threadIdx.x; d < DIMK; d += blockDim.x) sS[d] = g_S[i*DIMK + d];
    __syncthreads();
    int w = threadIdx.x >> 5, lane = threadIdx.x & 31;
    for (int j = w; j < 50; j += 8) {
        const float* tj = t + (long long)j*DIMK;
        float s = 0.f;
        for (int d = lane; d < DIMK; d += 32) s += sS[d]*tj[d];
        #pragma unroll
        for (int o = 16; o > 0; o >>= 1) s += __shfl_down_sync(0xffffffff, s, o);
        if (lane == 0) slog[j] = s * 0.03125f;
    }
    __syncthreads();
    if (threadIdx.x == 0) {
        float mx = slog[0];
        for (int j = 1; j < 50; j++) mx = fmaxf(mx, slog[j]);
        float sum = 0.f;
        for (int j = 0; j < 50; j++) { float e = expf(slog[j]-mx); slog[j]=e; sum+=e; }
        float inv = 1.f/sum;
        for (int j = 0; j < 50; j++) slog[j] *= inv;
    }
    __syncthreads();
    int mblk = i >> 7, mloc = i & 127;
    __half* cp = (__half*)g_CTXp;
    for (int d = threadIdx.x; d < DIMK; d += blockDim.x) {
        float c = 0.f;
        #pragma unroll 10
        for (int j = 0; j < 50; j++) c += slog[j]*t[(long long)j*DIMK + d];
        int chunk = d >> 5, kp = (d & 31) >> 1;
        cp[(((long long)(mblk*32 + chunk)*16 + kp)*128 + mloc)*2 + (d&1)] = __float2half_rn(c);
    }
}

// ---------------- final EMA fuse ----------------
__global__ void fuse_kernel(const float* __restrict__ bdd,
                            const float* __restrict__ momentum,
                            float* __restrict__ out)
{
    int n = blockIdx.x;
    float mom = *momentum;
    const int order[6] = {2,0,1,5,3,4};
    for (int d = threadIdx.x; d < DIMK; d += blockDim.x) {
        float e = bdd[d];
        #pragma unroll
        for (int k = 0; k < 6; k++) {
            int c = order[k];
            int ii = n*NCC + c;
            if (g_valid[ii]) e = mom*e + (1.f - mom)*g_EMB[(long long)ii*DIMK + d];
        }
        out[n*DIMK + d] = e;
    }
}

// ---------------- launch ----------------
static inline void* symv(const void* s) {
    void* p = nullptr; cudaGetSymbolAddress(&p, s); return p;
}
#define SMEM128 (3*(16*(128+8) + 16*136)*4)
#define SMEM64  (3*(16*(64+8)  + 16*136)*4)

extern "C" void kernel_launch(void* const* d_in, const int* in_sizes, int n_in,
                              void* d_out, int out_size)
{
    const float* camera_imgs = (const float*)d_in[0];
    const float* pred_boxes  = (const float*)d_in[1];
    const float* img_aug     = (const float*)d_in[2];
    const float* lidar_aug   = (const float*)d_in[3];
    const float* lidar2img   = (const float*)d_in[4];
    const float* momentum    = (const float*)d_in[5];
    const float* bdd         = (const float*)d_in[6];
    const float* theta_w     = (const float*)d_in[7];
    const float* theta_b     = (const float*)d_in[8];
    const float* conv1       = (const float*)d_in[9];
    const float* conv2       = (const float*)d_in[10];
    const float* conv3       = (const float*)d_in[11];
    const float* pos_embed   = (const float*)d_in[12];
    const float* wq          = (const float*)d_in[13];
    const float* wk          = (const float*)d_in[14];
    const float* wv          = (const float*)d_in[15];
    const float* wo          = (const float*)d_in[16];
    float* out = (float*)d_out;

    unsigned* pwqp = (unsigned*)symv(g_wqp);
    unsigned* pwvp = (unsigned*)symv(g_wvp);
    unsigned* pwkT = (unsigned*)symv(g_wkTp);
    unsigned* pwop = (unsigned*)symv(g_wop);
    unsigned* pMp  = (unsigned*)symv(g_Mp);
    unsigned* pWvop= (unsigned*)symv(g_Wvop);
    unsigned* pw1  = (unsigned*)symv(g_w1p);
    unsigned* pw2  = (unsigned*)symv(g_w2p);
    unsigned* pw3  = (unsigned*)symv(g_w3p);
    unsigned* ptok0= (unsigned*)symv(g_tok0p);
    unsigned* pCTX = (unsigned*)symv(g_CTXp);
    __half* pcrops = (__half*)symv(g_cropsh);
    __half* ph1    = (__half*)symv(g_h1h);
    __half* ph2    = (__half*)symv(g_h2h);
    float*  ph3    = (float*)symv(g_h3);
    float*  pS     = (float*)symv(g_S);
    float*  pEMB   = (float*)symv(g_EMB);

    cudaFuncSetAttribute(hgemm<0,128,false,2>, cudaFuncAttributeMaxDynamicSharedMemorySize, SMEM128);
    cudaFuncSetAttribute(hgemm<0,128,false,0>, cudaFuncAttributeMaxDynamicSharedMemorySize, SMEM128);
    cudaFuncSetAttribute(hgemm<1,64, true, 1>, cudaFuncAttributeMaxDynamicSharedMemorySize, SMEM64);
    cudaFuncSetAttribute(hgemm<2,128,true, 1>, cudaFuncAttributeMaxDynamicSharedMemorySize, SMEM128);
    cudaFuncSetAttribute(hgemm<3,128,true, 0>, cudaFuncAttributeMaxDynamicSharedMemorySize, SMEM128);

    // ---- pack weights ----
    packA_kernel<<<2048,256>>>(wq, pwqp, 1024, 1024, 128, 1024, 512LL*1024);
    packA_kernel<<<2048,256>>>(wv, pwvp, 1024, 1024, 128, 1024, 512LL*1024);
    packBd_kernel<<<2048,256>>>(wk, pwkT, 1024, 1024, 1);
    packBd_kernel<<<2048,256>>>(wo, pwop, 1024, 1024, 0);
    packA_kernel<<<20,256>>>(conv1, pw1, 64, K1, 64, 160, 64LL*80);
    packA_kernel<<<288,256>>>(conv2, pw2, 256, K2, 128, 576, 256LL*288);
    packA_kernel<<<4608,256>>>(conv3, pw3, 1024, K3, 128, 2304, 1024LL*1152);

    // ---- M = wq@wk^T ; Wvo = wv@wo  (outputs in packed-dense-B form) ----
    hgemm<0,128,false,2><<<dim3(8,8),256,SMEM128>>>(pwqp, pwkT, pMp, 1024, 1024, 1024, 1024);
    hgemm<0,128,false,2><<<dim3(8,8),256,SMEM128>>>(pwvp, pwop, pWvop, 1024, 1024, 1024, 1024);

    theta_kernel<<<2,192>>>(pred_boxes, lidar_aug, lidar2img, img_aug, theta_w, theta_b);
    {
        long long total = (long long)NIMG*CROPS*CROPS;
        sample_kernel<<<(unsigned)((total+255)/256),256>>>(camera_imgs);
    }

    // conv1: M=64 (BM=64), K=147 pad 160
    hgemm<1,64,true,1><<<dim3((unsigned)(N1/128),1),256,SMEM64>>>(pw1, pcrops, ph1, 160, K1, 0, (int)N1);
    // conv2: M=256, K=576
    hgemm<2,128,true,1><<<dim3((unsigned)(N2/128),2),256,SMEM128>>>(pw2, ph1, ph2, 576, K2, 0, (int)N2);
    // conv3: M=1024, K=2304 -> float h3
    hgemm<3,128,true,0><<<dim3((unsigned)(N3/128),8),256,SMEM128>>>(pw3, ph2, ph3, 2304, K3, 0, (int)N3);

    tok_kernel<<<NIMG,256>>>(pos_embed);

    // S = tok0 @ M
    hgemm<0,128,false,0><<<dim3(8,3),256,SMEM128>>>(ptok0, pMp, pS, 1024, 1024, 1024, DIMK);

    attn_kernel<<<NIMG,256>>>();

    // EMB = CTX @ Wvo
    hgemm<0,128,false,0><<<dim3(8,3),256,SMEM128>>>(pCTX, pWvop, pEMB, 1024, 1024, 1024, DIMK);

    fuse_kernel<<<NBOX,256>>>(bdd, momentum, out);
}

// round 8
// speedup vs baseline: 2.2507x; 1.3116x over previous
#include <cuda_runtime.h>
#include <cuda_fp16.h>
#include <math.h>

#define DIMK   1024
#define IMG_H  512
#define IMG_W  1408
#define CROPS  224
#define NCC    6
#define NBB    32
#define NBOX   64
#define NIMG   384
#define O1 56
#define O2 14
#define O3 7
#define N1 ((long long)NIMG*O1*O1)   // 1204224
#define N2 ((long long)NIMG*O2*O2)   // 75264
#define N3 ((long long)NIMG*O3*O3)   // 18816
#define K1 147
#define K2 576
#define K3 2304
// padded crops: [ch][img][227][228], halo zero (x,y in [-1,225])
#define CP_PW 228
#define CP_IMG (227*228)             // 51756
#define CP_CH  (NIMG*CP_IMG)         // 19874304
// padded h2: [ic][img][15][15]
#define H2P_IMG 225
#define H2P_IC  (NIMG*H2P_IMG)       // 86400

// ---------------- scratch ----------------
__device__ float  g_theta[NIMG*6];
__device__ int    g_valid[NIMG];
__device__ __align__(16) __half g_cropsp[3LL*CP_CH];        // padded crops
__device__ __half g_h1h[64LL*N1];
__device__ __align__(16) __half g_h2p[256LL*H2P_IC];        // padded h2
__device__ float  g_h3[1024LL*N3];
__device__ float  g_tok[(long long)NIMG*50*DIMK];
__device__ float  g_S[NIMG*DIMK];
__device__ float  g_EMB[NIMG*DIMK];
// packed (u32 = 2 halves along k)
__device__ unsigned g_wqp[512*1024], g_wvp[512*1024];
__device__ unsigned g_wkTp[512*1024], g_wop[512*1024];
__device__ unsigned g_Mp[512*1024], g_Wvop[512*1024];
__device__ unsigned g_w1p[64*80];
__device__ unsigned g_w2p[256*288];
__device__ unsigned g_w3p[1024*1152];
__device__ unsigned g_tok0p[384*512];
__device__ unsigned g_CTXp[384*512];

// ---------------- zero fill ----------------
__global__ void zero_kernel(ulonglong2* __restrict__ p, long long n16)
{
    long long i = (long long)blockIdx.x*blockDim.x + threadIdx.x;
    long long stride = (long long)gridDim.x*blockDim.x;
    ulonglong2 z; z.x = 0; z.y = 0;
    for (; i < n16; i += stride) p[i] = z;
}

// ---------------- pack kernels ----------------
__global__ void packA_kernel(const float* __restrict__ src, unsigned* __restrict__ dst,
                             int Ms, int Ks, int BMp, int Kpad, long long total)
{
    long long i = (long long)blockIdx.x*256 + threadIdx.x;
    if (i >= total) return;
    int NCH = Kpad/32;
    int mloc = (int)(i % BMp); long long r = i / BMp;
    int kp = (int)(r % 16); r /= 16;
    int chunk = (int)(r % NCH); int mblk = (int)(r / NCH);
    int m = mblk*BMp + mloc, k = chunk*32 + kp*2;
    float v0 = (m < Ms && k   < Ks) ? src[(long long)m*Ks + k]   : 0.f;
    float v1 = (m < Ms && k+1 < Ks) ? src[(long long)m*Ks + k+1] : 0.f;
    __half2 h = __floats2half2_rn(v0, v1);
    dst[i] = *reinterpret_cast<unsigned*>(&h);
}
__global__ void packBd_kernel(const float* __restrict__ src, unsigned* __restrict__ dst,
                              int Kd, int Nd, int transb)
{
    long long i = (long long)blockIdx.x*256 + threadIdx.x;
    if (i >= (long long)(Kd/2)*Nd) return;
    int n = (int)(i % Nd); long long r = i / Nd;
    int kp = (int)(r % 16); int chunk = (int)(r / 16);
    int k = chunk*32 + kp*2;
    float v0 = transb ? src[(long long)n*Kd + k]   : src[(long long)k*Nd + n];
    float v1 = transb ? src[(long long)n*Kd + k+1] : src[(long long)(k+1)*Nd + n];
    __half2 h = __floats2half2_rn(v0, v1);
    dst[i] = *reinterpret_cast<unsigned*>(&h);
}

// ---------------- theta ----------------
__global__ void theta_kernel(const float* __restrict__ boxes, const float* __restrict__ la,
                             const float* __restrict__ l2i, const float* __restrict__ aug,
                             const float* __restrict__ thw, const float* __restrict__ thb)
{
    int t = blockIdx.x*blockDim.x + threadIdx.x;
    if (t >= NIMG) return;
    int c = t % NCC; int n = t / NCC; int b = n / NBB; int nb = n % NBB;
    const float* bx = boxes + (b*NBB + nb)*9;
    float r[4];
    #pragma unroll
    for (int i = 0; i < 4; i++) {
        float s = thb[i];
        #pragma unroll
        for (int j = 0; j < 9; j++) s += bx[j]*thw[i*9+j];
        r[i] = tanhf(s);
    }
    const float* L = la + b*16;
    float cx = bx[0]-L[3], cy = bx[1]-L[7], cz = bx[2]-L[11];
    float a00=L[0],a01=L[1],a02=L[2],a10=L[4],a11=L[5],a12=L[6],a20=L[8],a21=L[9],a22=L[10];
    float det = a00*(a11*a22-a12*a21) - a01*(a10*a22-a12*a20) + a02*(a10*a21-a11*a20);
    float id = 1.f/det;
    float x = ((a11*a22-a12*a21)*cx + (a02*a21-a01*a22)*cy + (a01*a12-a02*a11)*cz)*id;
    float y = ((a12*a20-a10*a22)*cx + (a00*a22-a02*a20)*cy + (a02*a10-a00*a12)*cz)*id;
    float z = ((a10*a21-a11*a20)*cx + (a01*a20-a00*a21)*cy + (a00*a11-a01*a10)*cz)*id;
    const float* P = l2i + (b*NCC + c)*16;
    float px = P[0]*x + P[1]*y + P[2]*z  + P[3];
    float py = P[4]*x + P[5]*y + P[6]*z  + P[7];
    float pz = P[8]*x + P[9]*y + P[10]*z + P[11];
    float zz = fminf(fmaxf(pz, 1e-5f), 100000.f);
    float qx = px/zz, qy = py/zz;
    const float* A = aug + (b*NCC + c)*16;
    float ux = A[0]*qx + A[1]*qy + A[2]*zz + A[3];
    float uy = A[4]*qx + A[5]*qy + A[6]*zz + A[7];
    int on = (uy < (float)IMG_H) && (uy >= 0.f) && (ux < (float)IMG_W) && (ux >= 0.f);
    g_theta[t*6+0]=r[0]; g_theta[t*6+1]=r[1]; g_theta[t*6+2]=ux/(float)IMG_W*2.f-1.f;
    g_theta[t*6+3]=r[2]; g_theta[t*6+4]=r[3]; g_theta[t*6+5]=uy/(float)IMG_H*2.f-1.f;
    g_valid[t] = on;
}

// ---------------- grid sample -> padded half crops ----------------
__global__ void sample_kernel(const float* __restrict__ imgs)
{
    long long idx = (long long)blockIdx.x*blockDim.x + threadIdx.x;
    if (idx >= (long long)NIMG*CROPS*CROPS) return;
    int x = (int)(idx % CROPS);
    int y = (int)((idx / CROPS) % CROPS);
    int ii = (int)(idx / (CROPS*CROPS));
    int c = ii % NCC; int n = ii / NCC; int b = n / NBB;
    float t0 = g_theta[ii*6+0], t1 = g_theta[ii*6+1], t2 = g_theta[ii*6+2];
    float t3 = g_theta[ii*6+3], t4 = g_theta[ii*6+4], t5 = g_theta[ii*6+5];
    float gx = (2.f*x + 1.f)/(float)CROPS - 1.f;
    float gy = (2.f*y + 1.f)/(float)CROPS - 1.f;
    float g0 = gx*t0 + gy*t1 + t2;
    float g1 = gx*t3 + gy*t4 + t5;
    float ixf = ((g0 + 1.f)*(float)IMG_W - 1.f)*0.5f;
    float iyf = ((g1 + 1.f)*(float)IMG_H - 1.f)*0.5f;
    float x0 = floorf(ixf), y0 = floorf(iyf);
    float wx = ixf - x0, wy = iyf - y0;
    float x1 = x0 + 1.f, y1 = y0 + 1.f;
    bool vx0 = (x0 >= 0.f) && (x0 <= (float)(IMG_W-1));
    bool vx1 = (x1 >= 0.f) && (x1 <= (float)(IMG_W-1));
    bool vy0 = (y0 >= 0.f) && (y0 <= (float)(IMG_H-1));
    bool vy1 = (y1 >= 0.f) && (y1 <= (float)(IMG_H-1));
    int xi0 = (int)fminf(fmaxf(x0,0.f),(float)(IMG_W-1));
    int xi1 = (int)fminf(fmaxf(x1,0.f),(float)(IMG_W-1));
    int yi0 = (int)fminf(fmaxf(y0,0.f),(float)(IMG_H-1));
    int yi1 = (int)fminf(fmaxf(y1,0.f),(float)(IMG_H-1));
    float w00=(1.f-wx)*(1.f-wy), w01=wx*(1.f-wy), w10=(1.f-wx)*wy, w11=wx*wy;
    const float* base = imgs + (long long)(b*NCC + c)*3LL*IMG_H*IMG_W;
    #pragma unroll
    for (int ch = 0; ch < 3; ch++) {
        const float* im = base + (long long)ch*IMG_H*IMG_W;
        float v00 = (vx0&&vy0) ? im[yi0*IMG_W + xi0] : 0.f;
        float v01 = (vx1&&vy0) ? im[yi0*IMG_W + xi1] : 0.f;
        float v10 = (vx0&&vy1) ? im[yi1*IMG_W + xi0] : 0.f;
        float v11 = (vx1&&vy1) ? im[yi1*IMG_W + xi1] : 0.f;
        g_cropsp[(long long)ch*CP_CH + (long long)ii*CP_IMG + (y+1)*CP_PW + (x+1)] =
            __float2half_rn(v00*w00 + v01*w01 + v10*w10 + v11*w11);
    }
}

// ---------------- cp.async helpers ----------------
__device__ __forceinline__ void cpasync16(unsigned dst, const void* src) {
    asm volatile("cp.async.cg.shared.global [%0], [%1], 16;\n"
        :: "r"(dst), "l"(src) : "memory");
}
#define CP_COMMIT() asm volatile("cp.async.commit_group;\n" ::: "memory")
#define CP_WAIT1()  asm volatile("cp.async.wait_group 1;\n" ::: "memory")

// =====================================================================
// Half-native pipelined GEMM, m16n8k16 fp16 MMA, fp32 accum.
// A: packed u32 [(mblk*NCH+chunk)*16+kp]*BM + mloc  (half2 k-pairs)
// B: LOADER 0 = dense packed u32 (cp.async)
//    LOADER 1/2/3 = implicit-im2col gather via warp-uniform smem offset
//    tables from zero-padded half sources (NO predicates, NO divisions).
// CW: 0 = float C, 1 = half C, 2 = packed-dense-B C, 3 = scatter to h2p
// =====================================================================
template<int LOADER, int BM, bool RELU, int CW>
__global__ __launch_bounds__(256) void hgemm(
    const unsigned* __restrict__ A, const void* __restrict__ Bp, void* __restrict__ Cp,
    int Kpad, int N, int ldc)
{
    constexpr int SROW = BM + 8;
    constexpr int ASZ  = 16*SROW;
    constexpr int BSZ  = 16*136;
    extern __shared__ unsigned smemU[];
    int2* sTab = (int2*)(smemU + 3*(ASZ+BSZ));

    const int tid = threadIdx.x;
    const int bx = blockIdx.x, by = blockIdx.y;
    const int lane = tid & 31, warp = tid >> 5;
    const int g = lane >> 2, tg = lane & 3;
    constexpr int WMC = BM/32;
    constexpr int WN  = 128/(8/WMC);
    constexpr int NT  = WN/8;
    const int wm = (warp % WMC)*32;
    const int wn = (warp / WMC)*WN;

    const int NCH = Kpad/32;
    const int T = NCH;

    const int nloc = tid & 127;
    const int ngl  = bx*128 + nloc;
    const int hsel = tid >> 7;
    const __half* Bh = (const __half*)Bp;
    const unsigned* Bu = (const unsigned*)Bp;

    // per-thread gather base (element offset into padded source)
    const __half* Bbase = Bh;
    if (LOADER == 1) {
        int img = ngl/3136, pos = ngl - img*3136;
        int oy = pos/56, ox = pos - oy*56;
        Bbase = Bh + ((long long)img*CP_IMG + oy*4*CP_PW + ox*4);
    } else if (LOADER == 2) {
        int img = ngl/196, pos = ngl - img*196;
        int oy = pos/14, ox = pos - oy*14;
        Bbase = Bh + ((long long)img*3136 + oy*4*56 + ox*4);
    } else if (LOADER == 3) {
        int img = ngl/49, pos = ngl - img*49;
        int oy = pos/7, ox = pos - oy*7;
        Bbase = Bh + ((long long)img*H2P_IMG + oy*2*15 + ox*2);
    }

    // build warp-uniform offset table (k -> element offset in padded src)
    if (LOADER != 0) {
        int TPK = Kpad/2;
        for (int kp = tid; kp < TPK; kp += 256) {
            int2 e;
            #pragma unroll
            for (int h = 0; h < 2; h++) {
                int k = kp*2 + h;
                int D = 0;
                if (LOADER == 1) {
                    if (k < K1) {
                        int ch = k/49, rr = k - ch*49;
                        int ky = rr/7, kx = rr - ky*7;
                        D = ch*CP_CH + ky*CP_PW + kx;
                    }
                } else if (LOADER == 2) {
                    int ic = k/9, rr = k - ic*9;
                    int ky = rr/3, kx = rr - ky*3;
                    D = ic*(int)N1 + ky*56 + kx;
                } else if (LOADER == 3) {
                    int ic = k/9, rr = k - ic*9;
                    int ky = rr/3, kx = rr - ky*3;
                    D = ic*H2P_IC + ky*15 + kx;
                }
                if (h == 0) e.x = D; else e.y = D;
            }
            sTab[kp] = e;
        }
        __syncthreads();
    }

    unsigned sbase = (unsigned)__cvta_generic_to_shared(smemU);

    unsigned Breg[8];
    auto gatherB = [&](int chunk) {
        #pragma unroll
        for (int j = 0; j < 8; j++) {
            int2 dd = sTab[chunk*16 + hsel*8 + j];      // warp-uniform broadcast
            unsigned v0 = (unsigned)__half_as_ushort(Bbase[dd.x]);
            unsigned v1 = (unsigned)__half_as_ushort(Bbase[dd.y]);
            Breg[j] = v0 | (v1 << 16);
        }
    };
    auto storeB = [&](int st) {
        unsigned* sB = smemU + st*(ASZ+BSZ) + ASZ;
        #pragma unroll
        for (int j = 0; j < 8; j++)
            sB[(hsel*8 + j)*136 + nloc] = Breg[j];
    };
    auto loadA_cp = [&](int st, int chunk) {
        unsigned sa = sbase + (unsigned)(st*(ASZ+BSZ)*4);
        constexpr int perkp = BM/4;
        constexpr int NTR = 16*perkp;
        #pragma unroll
        for (int i = 0; i < NTR/256; i++) {
            int e = tid + i*256;
            int kp = e / perkp, mq = (e % perkp)*4;
            const unsigned* src = A + ((long long)(by*NCH + chunk)*16 + kp)*BM + mq;
            cpasync16(sa + (unsigned)((kp*SROW + mq)*4), src);
        }
    };
    auto loadB_cp = [&](int st, int chunk) {
        unsigned sb = sbase + (unsigned)((st*(ASZ+BSZ) + ASZ)*4);
        #pragma unroll
        for (int i = 0; i < 2; i++) {
            int e = tid + i*256;
            int kp = e >> 5, nq = (e & 31)*4;
            const unsigned* src = Bu + (long long)(chunk*16 + kp)*N + bx*128 + nq;
            cpasync16(sb + (unsigned)((kp*136 + nq)*4), src);
        }
    };

    float acc[2][NT][4];
    #pragma unroll
    for (int i=0;i<2;i++)
        #pragma unroll
        for (int j=0;j<NT;j++)
            #pragma unroll
            for (int q=0;q<4;q++) acc[i][j][q] = 0.f;

    if (LOADER == 0) {
        loadA_cp(0,0); loadB_cp(0,0); CP_COMMIT();
        loadA_cp(1,1); loadB_cp(1,1); CP_COMMIT();
    } else {
        gatherB(0); storeB(0);
        gatherB(1);
        loadA_cp(0,0); CP_COMMIT();
        loadA_cp(1,1); CP_COMMIT();
    }

    for (int kt = 0; kt < T; kt++) {
        CP_WAIT1();
        __syncthreads();
        int kn = kt + 2;
        if (kn < T) {
            int stn = kn % 3;
            loadA_cp(stn, kn);
            if (LOADER == 0) loadB_cp(stn, kn);
        }
        CP_COMMIT();

        int st = kt % 3;
        const unsigned* sA = smemU + st*(ASZ+BSZ);
        const unsigned* sB = sA + ASZ;
        #pragma unroll
        for (int s = 0; s < 2; s++) {
            int kb = s*8;
            unsigned af[2][4];
            #pragma unroll
            for (int mt = 0; mt < 2; mt++) {
                int r1 = wm + mt*16 + g;
                af[mt][0] = sA[(kb+tg)*SROW + r1];
                af[mt][1] = sA[(kb+tg)*SROW + r1 + 8];
                af[mt][2] = sA[(kb+tg+4)*SROW + r1];
                af[mt][3] = sA[(kb+tg+4)*SROW + r1 + 8];
            }
            unsigned bf[NT][2];
            #pragma unroll
            for (int nt = 0; nt < NT; nt++) {
                int cc = wn + nt*8 + g;
                bf[nt][0] = sB[(kb+tg)*136 + cc];
                bf[nt][1] = sB[(kb+tg+4)*136 + cc];
            }
            #pragma unroll
            for (int mt = 0; mt < 2; mt++)
                #pragma unroll
                for (int nt = 0; nt < NT; nt++) {
                    asm volatile(
                        "mma.sync.aligned.m16n8k16.row.col.f32.f16.f16.f32 "
                        "{%0,%1,%2,%3}, {%4,%5,%6,%7}, {%8,%9}, {%0,%1,%2,%3};\n"
                        : "+f"(acc[mt][nt][0]), "+f"(acc[mt][nt][1]),
                          "+f"(acc[mt][nt][2]), "+f"(acc[mt][nt][3])
                        : "r"(af[mt][0]), "r"(af[mt][1]), "r"(af[mt][2]), "r"(af[mt][3]),
                          "r"(bf[nt][0]), "r"(bf[nt][1]));
                }
        }
        if (LOADER != 0) {
            if (kt+1 < T) storeB((kt+1) % 3);
            if (kt+2 < T) gatherB(kt+2);
        }
    }

    // epilogue
    #pragma unroll
    for (int mt = 0; mt < 2; mt++) {
        int r0 = by*BM + wm + mt*16 + g;
        #pragma unroll
        for (int nt = 0; nt < NT; nt++) {
            int c0 = bx*128 + wn + nt*8 + tg*2;
            float v0 = acc[mt][nt][0], v1 = acc[mt][nt][1];
            float v2 = acc[mt][nt][2], v3 = acc[mt][nt][3];
            if (RELU) { v0=fmaxf(v0,0.f); v1=fmaxf(v1,0.f); v2=fmaxf(v2,0.f); v3=fmaxf(v3,0.f); }
            if (CW == 0) {
                float* C = (float*)Cp;
                *reinterpret_cast<float2*>(C + (long long)r0*ldc + c0)     = make_float2(v0, v1);
                *reinterpret_cast<float2*>(C + (long long)(r0+8)*ldc + c0) = make_float2(v2, v3);
            } else if (CW == 1) {
                __half* C = (__half*)Cp;
                __half2 h0 = __floats2half2_rn(v0, v1);
                __half2 h1 = __floats2half2_rn(v2, v3);
                *reinterpret_cast<__half2*>(C + (long long)r0*ldc + c0)     = h0;
                *reinterpret_cast<__half2*>(C + (long long)(r0+8)*ldc + c0) = h1;
            } else if (CW == 2) {
                __half* C = (__half*)Cp;
                auto st1 = [&](int r, int c, float v) {
                    long long idx = ((long long)((r>>5)*16 + ((r>>1)&15))*N + c)*2 + (r&1);
                    C[idx] = __float2half_rn(v);
                };
                st1(r0,   c0,   v0); st1(r0,   c0+1, v1);
                st1(r0+8, c0,   v2); st1(r0+8, c0+1, v3);
            } else {  // CW==3: scatter to padded h2p  [ic][img][15][15]
                __half* C = (__half*)Cp;
                auto st2 = [&](int r, int c, float v) {
                    int img = c/196; int pos = c - img*196;
                    int oy = pos/14, ox = pos - oy*14;
                    C[(long long)r*H2P_IC + img*H2P_IMG + oy*15 + ox] = __float2half_rn(v);
                };
                st2(r0,   c0,   v0); st2(r0,   c0+1, v1);
                st2(r0+8, c0,   v2); st2(r0+8, c0+1, v3);
            }
        }
    }
}

// ---------------- tokens ----------------
__global__ void tok_kernel(const float* __restrict__ pos_embed)
{
    int i = blockIdx.x;
    int mblk = i >> 7, mloc = i & 127;
    __half* tp = (__half*)g_tok0p;
    for (int d = threadIdx.x; d < DIMK; d += blockDim.x) {
        const float* hp = g_h3 + (long long)d*N3 + (long long)i*49;
        float s = 0.f;
        #pragma unroll 7
        for (int p = 0; p < 49; p++) {
            float v = hp[p];
            s += v;
            g_tok[((long long)i*50 + 1 + p)*DIMK + d] = v + pos_embed[(1+p)*DIMK + d];
        }
        float t0 = s*(1.f/49.f) + pos_embed[d];
        g_tok[(long long)i*50*DIMK + d] = t0;
        int chunk = d >> 5, kp = (d & 31) >> 1;
        tp[(((long long)(mblk*32 + chunk)*16 + kp)*128 + mloc)*2 + (d&1)] = __float2half_rn(t0);
    }
}

// ---------------- attention ----------------
__global__ void attn_kernel()
{
    int i = blockIdx.x;
    __shared__ float sS[DIMK];
    __shared__ float slog[64];
    const float* t = g_tok + (long long)i*50*DIMK;
    for (int d = threadIdx.x; d < DIMK; d += blockDim.x) sS[d] = g_S[i*DIMK + d];
    __syncthreads();
    int w = threadIdx.x >> 5, lane = threadIdx.x & 31;
    for (int j = w; j < 50; j += 8) {
        const float* tj = t + (long long)j*DIMK;
        float s = 0.f;
        for (int d = lane; d < DIMK; d += 32) s += sS[d]*tj[d];
        #pragma unroll
        for (int o = 16; o > 0; o >>= 1) s += __shfl_down_sync(0xffffffff, s, o);
        if (lane == 0) slog[j] = s * 0.03125f;
    }
    __syncthreads();
    if (threadIdx.x == 0) {
        float mx = slog[0];
        for (int j = 1; j < 50; j++) mx = fmaxf(mx, slog[j]);
        float sum = 0.f;
        for (int j = 0; j < 50; j++) { float e = expf(slog[j]-mx); slog[j]=e; sum+=e; }
        float inv = 1.f/sum;
        for (int j = 0; j < 50; j++) slog[j] *= inv;
    }
    __syncthreads();
    int mblk = i >> 7, mloc = i & 127;
    __half* cp = (__half*)g_CTXp;
    for (int d = threadIdx.x; d < DIMK; d += blockDim.x) {
        float c = 0.f;
        #pragma unroll 10
        for (int j = 0; j < 50; j++) c += slog[j]*t[(long long)j*DIMK + d];
        int chunk = d >> 5, kp = (d & 31) >> 1;
        cp[(((long long)(mblk*32 + chunk)*16 + kp)*128 + mloc)*2 + (d&1)] = __float2half_rn(c);
    }
}

// ---------------- final EMA fuse ----------------
__global__ void fuse_kernel(const float* __restrict__ bdd,
                            const float* __restrict__ momentum,
                            float* __restrict__ out)
{
    int n = blockIdx.x;
    float mom = *momentum;
    const int order[6] = {2,0,1,5,3,4};
    for (int d = threadIdx.x; d < DIMK; d += blockDim.x) {
        float e = bdd[d];
        #pragma unroll
        for (int k = 0; k < 6; k++) {
            int c = order[k];
            int ii = n*NCC + c;
            if (g_valid[ii]) e = mom*e + (1.f - mom)*g_EMB[(long long)ii*DIMK + d];
        }
        out[n*DIMK + d] = e;
    }
}

// ---------------- launch ----------------
static inline void* symv(const void* s) {
    void* p = nullptr; cudaGetSymbolAddress(&p, s); return p;
}
#define ABSZ128 ((16*(128+8) + 16*136)*4)
#define ABSZ64  ((16*(64+8)  + 16*136)*4)
#define SMEM_D   (3*ABSZ128)            // dense
#define SMEM_C1  (3*ABSZ64  + 80*8)
#define SMEM_C2  (3*ABSZ128 + 288*8)
#define SMEM_C3  (3*ABSZ128 + 1152*8)

extern "C" void kernel_launch(void* const* d_in, const int* in_sizes, int n_in,
                              void* d_out, int out_size)
{
    const float* camera_imgs = (const float*)d_in[0];
    const float* pred_boxes  = (const float*)d_in[1];
    const float* img_aug     = (const float*)d_in[2];
    const float* lidar_aug   = (const float*)d_in[3];
    const float* lidar2img   = (const float*)d_in[4];
    const float* momentum    = (const float*)d_in[5];
    const float* bdd         = (const float*)d_in[6];
    const float* theta_w     = (const float*)d_in[7];
    const float* theta_b     = (const float*)d_in[8];
    const float* conv1       = (const float*)d_in[9];
    const float* conv2       = (const float*)d_in[10];
    const float* conv3       = (const float*)d_in[11];
    const float* pos_embed   = (const float*)d_in[12];
    const float* wq          = (const float*)d_in[13];
    const float* wk          = (const float*)d_in[14];
    const float* wv          = (const float*)d_in[15];
    const float* wo          = (const float*)d_in[16];
    float* out = (float*)d_out;

    unsigned* pwqp = (unsigned*)symv(g_wqp);
    unsigned* pwvp = (unsigned*)symv(g_wvp);
    unsigned* pwkT = (unsigned*)symv(g_wkTp);
    unsigned* pwop = (unsigned*)symv(g_wop);
    unsigned* pMp  = (unsigned*)symv(g_Mp);
    unsigned* pWvop= (unsigned*)symv(g_Wvop);
    unsigned* pw1  = (unsigned*)symv(g_w1p);
    unsigned* pw2  = (unsigned*)symv(g_w2p);
    unsigned* pw3  = (unsigned*)symv(g_w3p);
    unsigned* ptok0= (unsigned*)symv(g_tok0p);
    unsigned* pCTX = (unsigned*)symv(g_CTXp);
    __half* pcropsp= (__half*)symv(g_cropsp);
    __half* ph1    = (__half*)symv(g_h1h);
    __half* ph2p   = (__half*)symv(g_h2p);
    float*  ph3    = (float*)symv(g_h3);
    float*  pS     = (float*)symv(g_S);
    float*  pEMB   = (float*)symv(g_EMB);

    cudaFuncSetAttribute(hgemm<0,128,false,2>, cudaFuncAttributeMaxDynamicSharedMemorySize, SMEM_D);
    cudaFuncSetAttribute(hgemm<0,128,false,0>, cudaFuncAttributeMaxDynamicSharedMemorySize, SMEM_D);
    cudaFuncSetAttribute(hgemm<1,64, true, 1>, cudaFuncAttributeMaxDynamicSharedMemorySize, SMEM_C1);
    cudaFuncSetAttribute(hgemm<2,128,true, 3>, cudaFuncAttributeMaxDynamicSharedMemorySize, SMEM_C2);
    cudaFuncSetAttribute(hgemm<3,128,true, 0>, cudaFuncAttributeMaxDynamicSharedMemorySize, SMEM_C3);

    // ---- zero padded buffers ----
    zero_kernel<<<2048,256>>>((ulonglong2*)pcropsp, (3LL*CP_CH*2)/16);
    zero_kernel<<<1024,256>>>((ulonglong2*)ph2p, (256LL*H2P_IC*2)/16);

    // ---- pack weights ----
    packA_kernel<<<2048,256>>>(wq, pwqp, 1024, 1024, 128, 1024, 512LL*1024);
    packA_kernel<<<2048,256>>>(wv, pwvp, 1024, 1024, 128, 1024, 512LL*1024);
    packBd_kernel<<<2048,256>>>(wk, pwkT, 1024, 1024, 1);
    packBd_kernel<<<2048,256>>>(wo, pwop, 1024, 1024, 0);
    packA_kernel<<<20,256>>>(conv1, pw1, 64, K1, 64, 160, 64LL*80);
    packA_kernel<<<288,256>>>(conv2, pw2, 256, K2, 128, 576, 256LL*288);
    packA_kernel<<<4608,256>>>(conv3, pw3, 1024, K3, 128, 2304, 1024LL*1152);

    // ---- M = wq@wk^T ; Wvo = wv@wo ----
    hgemm<0,128,false,2><<<dim3(8,8),256,SMEM_D>>>(pwqp, pwkT, pMp, 1024, 1024, 1024);
    hgemm<0,128,false,2><<<dim3(8,8),256,SMEM_D>>>(pwvp, pwop, pWvop, 1024, 1024, 1024);

    theta_kernel<<<2,192>>>(pred_boxes, lidar_aug, lidar2img, img_aug, theta_w, theta_b);
    {
        long long total = (long long)NIMG*CROPS*CROPS;
        sample_kernel<<<(unsigned)((total+255)/256),256>>>(camera_imgs);
    }

    // conv1: M=64 (BM=64), Kpad=160, gather from padded crops
    hgemm<1,64,true,1><<<dim3((unsigned)(N1/128),1),256,SMEM_C1>>>(pw1, pcropsp, ph1, 160, 0, (int)N1);
    // conv2: M=256, K=576, gather from h1 -> scatter to padded h2p
    hgemm<2,128,true,3><<<dim3((unsigned)(N2/128),2),256,SMEM_C2>>>(pw2, ph1, ph2p, 576, 0, 0);
    // conv3: M=1024, K=2304, gather from padded h2p -> float h3
    hgemm<3,128,true,0><<<dim3((unsigned)(N3/128),8),256,SMEM_C3>>>(pw3, ph2p, ph3, 2304, 0, (int)N3);

    tok_kernel<<<NIMG,256>>>(pos_embed);

    // S = tok0 @ M
    hgemm<0,128,false,0><<<dim3(8,3),256,SMEM_D>>>(ptok0, pMp, pS, 1024, 1024, DIMK);

    attn_kernel<<<NIMG,256>>>();

    // EMB = CTX @ Wvo
    hgemm<0,128,false,0><<<dim3(8,3),256,SMEM_D>>>(pCTX, pWvop, pEMB, 1024, 1024, DIMK);

    fuse_kernel<<<NBOX,256>>>(bdd, momentum, out);
}